// round 9
// baseline (speedup 1.0000x reference)
#include <cuda_runtime.h>
#include <cuda_fp16.h>
#include <cstdint>
#include <math.h>

#define NNODE 8192
#define DIN   512
#define DLAT  128
#define NSLOT 16               // fp16 split slots per latent k
#define KSPL  (DLAT * NSLOT)   // 2048

static const int OUT_NN = NNODE * NNODE;           // 67108864
static const int OUT_NL = NNODE * DLAT;            // 1048576

// ---------------- scratch (device globals; no allocation allowed) ----------
__device__ float g_T[3][DIN][DLAT];                // softmaxed transforms
__device__ float g_zd[NNODE * DLAT];
__device__ float g_ig[NNODE * DLAT];               // 1/(gd+SMALL)
__device__ float g_id[NNODE * DLAT];               // 1/(dd+SMALL)
__device__ __half g_U[(size_t)NNODE * KSPL];       // split-U (32 MB)
__device__ __half g_V[(size_t)NNODE * KSPL];       // split-V (32 MB)

// ---------------- K1: column softmax of the three W matrices ---------------
__global__ void softmax_cols(const float* __restrict__ Wz,
                             const float* __restrict__ Wg,
                             const float* __restrict__ Wd) {
    int mat = blockIdx.x >> 7;        // 0..2
    int col = blockIdx.x & 127;
    const float* W = (mat == 0) ? Wz : (mat == 1) ? Wg : Wd;
    int t = threadIdx.x;              // 128 threads
    __shared__ float red[128];

    float v[4];
#pragma unroll
    for (int r = 0; r < 4; r++) v[r] = W[(t + r * 128) * DLAT + col];

    float m = fmaxf(fmaxf(v[0], v[1]), fmaxf(v[2], v[3]));
    red[t] = m; __syncthreads();
    for (int s = 64; s > 0; s >>= 1) {
        if (t < s) red[t] = fmaxf(red[t], red[t + s]);
        __syncthreads();
    }
    m = red[0]; __syncthreads();

    float e[4], sum = 0.f;
#pragma unroll
    for (int r = 0; r < 4; r++) { e[r] = expf(v[r] - m); sum += e[r]; }
    red[t] = sum; __syncthreads();
    for (int s = 64; s > 0; s >>= 1) {
        if (t < s) red[t] += red[t + s];
        __syncthreads();
    }
    float inv = 1.f / red[0];
#pragma unroll
    for (int r = 0; r < 4; r++) g_T[mat][t + r * 128][col] = e[r] * inv;
}

// ---------------- K2a: zd / gd / dd GEMMs (fp32 SIMT) ----------------------
__global__ __launch_bounds__(256) void gemm_small(const float* __restrict__ z,
                                                  const float* __restrict__ gamma,
                                                  const float* __restrict__ delta,
                                                  float* __restrict__ out) {
    __shared__ float As[32][65];      // [k][m] transposed
    __shared__ float Bs[32][128];

    int which = blockIdx.y;
    const float* A = (which == 0) ? z : (which == 1) ? gamma : delta;
    const float* B = &g_T[which][0][0];
    int r0 = blockIdx.x * 64;

    int tid = threadIdx.x;
    int ty = tid >> 4, tx = tid & 15;

    float acc[4][8];
#pragma unroll
    for (int i = 0; i < 4; i++)
#pragma unroll
        for (int j = 0; j < 8; j++) acc[i][j] = 0.f;

    for (int kc = 0; kc < DIN / 32; kc++) {
#pragma unroll
        for (int it = 0; it < 2; it++) {
            int linear = tid + it * 256;          // 0..511
            int arow = linear >> 3, ac4 = linear & 7;
            float4 va = *reinterpret_cast<const float4*>(
                &A[(r0 + arow) * DIN + kc * 32 + ac4 * 4]);
            As[ac4 * 4 + 0][arow] = va.x;
            As[ac4 * 4 + 1][arow] = va.y;
            As[ac4 * 4 + 2][arow] = va.z;
            As[ac4 * 4 + 3][arow] = va.w;
        }
#pragma unroll
        for (int it = 0; it < 4; it++) {
            int linear = tid + it * 256;          // 0..1023
            int brow = linear >> 5, bc4 = linear & 31;
            *reinterpret_cast<float4*>(&Bs[brow][bc4 * 4]) =
                *reinterpret_cast<const float4*>(&B[(kc * 32 + brow) * DLAT + bc4 * 4]);
        }
        __syncthreads();

#pragma unroll
        for (int kk = 0; kk < 32; kk++) {
            float a[4];
#pragma unroll
            for (int i = 0; i < 4; i++) a[i] = As[kk][ty * 4 + i];
            float4 b0 = *reinterpret_cast<float4*>(&Bs[kk][tx * 4]);
            float4 b1 = *reinterpret_cast<float4*>(&Bs[kk][64 + tx * 4]);
#pragma unroll
            for (int i = 0; i < 4; i++) {
                acc[i][0] = fmaf(a[i], b0.x, acc[i][0]);
                acc[i][1] = fmaf(a[i], b0.y, acc[i][1]);
                acc[i][2] = fmaf(a[i], b0.z, acc[i][2]);
                acc[i][3] = fmaf(a[i], b0.w, acc[i][3]);
                acc[i][4] = fmaf(a[i], b1.x, acc[i][4]);
                acc[i][5] = fmaf(a[i], b1.y, acc[i][5]);
                acc[i][6] = fmaf(a[i], b1.z, acc[i][6]);
                acc[i][7] = fmaf(a[i], b1.w, acc[i][7]);
            }
        }
        __syncthreads();
    }

#pragma unroll
    for (int i = 0; i < 4; i++) {
        int node = r0 + ty * 4 + i;
#pragma unroll
        for (int j = 0; j < 8; j++) {
            int col = (j < 4) ? (tx * 4 + j) : (64 + tx * 4 + (j - 4));
            int idx = node * DLAT + col;
            float v = acc[i][j];
            if (which == 0) {
                g_zd[idx] = v;
                out[OUT_NN + idx] = v;
            } else if (which == 1) {
                out[OUT_NN + OUT_NL + idx] = v;
                g_ig[idx] = 1.f / (v + 1e-16f);
            } else {
                out[OUT_NN + 2 * OUT_NL + idx] = v;
                g_id[idx] = 1.f / (v + 1e-16f);
            }
        }
    }
}

// ---------------- K2b: build telescoped fp16-split U, V ---------------------
__device__ __forceinline__ void split2(float x, float& h, float& l) {
    h = __half2float(__float2half_rn(x));
    l = x - h;
}

__global__ __launch_bounds__(128) void prep_split(const float* __restrict__ pwg,
                                                  const float* __restrict__ pwd) {
    int i = blockIdx.x;
    int k = threadIdx.x;          // 0..127
    float zd = g_zd[i * DLAT + k];
    float ig = g_ig[i * DLAT + k];
    float id = g_id[i * DLAT + k];
    float z2 = zd * zd;
    float wgn = (*pwg) * 8192.0f;
    float wdn = (*pwd) * 8192.0f;

    float u1 = -(wgn * ig * z2);      // pairs with v=1
    float v6 = wdn * z2 * id;         // pairs with u=-1
    float U2 = (2.f * wgn * ig * zd) * 0.03125f;
    float V2 = zd * 32.f;
    float U3 = -(wgn * ig) * 0.0078125f;
    float V3 = z2 * 128.f;
    float U4 = -z2 * 128.f;
    float V4 = (wdn * id) * 0.0078125f;
    float U5 = (2.f * zd) * 16.f;
    float V5 = (wdn * zd * id) * 0.0625f;

    const float S  = 256.f;
    const float SI = 0.00390625f;

    float us[NSLOT], vs[NSLOT];
    float h, l;

    split2(u1, h, l);
    us[0] = h;       vs[0] = 1.f;
    us[1] = l * S;   vs[1] = SI;

#define PG(b, U, V) { float uh, ul, vh, vl; split2(U, uh, ul); split2(V, vh, vl); \
    us[(b)+0] = uh;      vs[(b)+0] = vh;       \
    us[(b)+1] = uh * SI; vs[(b)+1] = vl * S;   \
    us[(b)+2] = ul * S;  vs[(b)+2] = vh * SI; }

    PG(2,  U2, V2)
    PG(5,  U3, V3)
    PG(8,  U4, V4)
    PG(11, U5, V5)
#undef PG

    split2(v6, h, l);
    us[14] = -1.f;  vs[14] = h;
    us[15] = -SI;   vs[15] = l * S;

    __half hu[NSLOT], hv[NSLOT];
#pragma unroll
    for (int s = 0; s < NSLOT; s++) {
        hu[s] = __float2half_rn(us[s]);
        hv[s] = __float2half_rn(vs[s]);
    }
    size_t base = (size_t)i * KSPL + (size_t)k * NSLOT;
    *reinterpret_cast<uint4*>(&g_U[base])     = *reinterpret_cast<uint4*>(&hu[0]);
    *reinterpret_cast<uint4*>(&g_U[base + 8]) = *reinterpret_cast<uint4*>(&hu[8]);
    *reinterpret_cast<uint4*>(&g_V[base])     = *reinterpret_cast<uint4*>(&hv[0]);
    *reinterpret_cast<uint4*>(&g_V[base + 8]) = *reinterpret_cast<uint4*>(&hv[8]);
}

// ---------------- K3: 8192x8192x2048 fp16 mma.sync GEMM --------------------
// Block tile 128x256, warp grid 2x4, warp tile 64x64 (4x8 m16n8 frags).
// cp.async double-buffered K=32 chunks; B loaded with ldmatrix x4 (n16k16).
__device__ __forceinline__ uint32_t smem_u32(const void* p) {
    uint32_t a;
    asm("{ .reg .u64 t; cvta.to.shared.u64 t, %1; cvt.u32.u64 %0, t; }"
        : "=r"(a) : "l"(p));
    return a;
}
__device__ __forceinline__ void ldsm_x4(uint32_t& r0, uint32_t& r1,
                                        uint32_t& r2, uint32_t& r3, uint32_t addr) {
    asm volatile("ldmatrix.sync.aligned.m8n8.x4.shared.b16 {%0,%1,%2,%3}, [%4];\n"
                 : "=r"(r0), "=r"(r1), "=r"(r2), "=r"(r3) : "r"(addr));
}
__device__ __forceinline__ void mma_fp16(float& c0, float& c1, float& c2, float& c3,
                                         uint32_t a0, uint32_t a1, uint32_t a2, uint32_t a3,
                                         uint32_t b0, uint32_t b1) {
    asm volatile("mma.sync.aligned.m16n8k16.row.col.f32.f16.f16.f32 "
                 "{%0,%1,%2,%3}, {%4,%5,%6,%7}, {%8,%9}, {%0,%1,%2,%3};\n"
                 : "+f"(c0), "+f"(c1), "+f"(c2), "+f"(c3)
                 : "r"(a0), "r"(a1), "r"(a2), "r"(a3), "r"(b0), "r"(b1));
}
#define CP_ASYNC16(sm, gm) \
    asm volatile("cp.async.cg.shared.global [%0], [%1], 16;\n" :: "r"(sm), "l"(gm))
#define CP_COMMIT() asm volatile("cp.async.commit_group;\n" ::: "memory")
#define CP_WAIT(n)  asm volatile("cp.async.wait_group %0;\n" :: "n"(n) : "memory")

__device__ __forceinline__ float fast_sigmoid(float x) {
    if (x < -88.f) return 0.f;
    return 1.f / (1.f + expf(-x));
}

#define SPAD   40                 // halves per smem row (80 B; 20-bank shift)
#define TM     128
#define TN     256
#define KC     32
#define NCHUNK (KSPL / KC)        // 64
#define SA_BYTES (TM * SPAD * 2)  // 10240
#define SB_BYTES (TN * SPAD * 2)  // 20480
#define SMEM_PAIR_TOTAL (2 * SA_BYTES + 2 * SB_BYTES)   // 61440

__global__ __launch_bounds__(256, 1) void pair_kernel(float* __restrict__ out,
                                                      const float* __restrict__ pb) {
    extern __shared__ __align__(128) char smem[];
    uint32_t sbase = smem_u32(smem);

    int tid = threadIdx.x;
    int lane = tid & 31, wid = tid >> 5;
    int warpM = wid >> 2, warpN = wid & 3;   // 2 x 4 warps; warp tile 64x64

    // tile swizzle: groups of 8 brows x 32 bcols keep wave working set in L2
    int bx = blockIdx.x;                     // 0..2047 (64 brows x 32 bcols)
    int brow = ((bx >> 8) << 3) + ((bx & 255) >> 5);
    int bcol = bx & 31;
    int i0 = brow * TM, j0 = bcol * TN;

    float acc[4][8][4];
#pragma unroll
    for (int a = 0; a < 4; a++)
#pragma unroll
        for (int b = 0; b < 8; b++)
#pragma unroll
            for (int c = 0; c < 4; c++) acc[a][b][c] = 0.f;

    // cp.async lane mapping: quad index q -> row = q>>2, qi = q&3 (16B each)
    int arow[2], aqi[2], brow_[4], bqi[4];
#pragma unroll
    for (int it = 0; it < 2; it++) { int q = tid + it * 256; arow[it] = q >> 2; aqi[it] = q & 3; }
#pragma unroll
    for (int it = 0; it < 4; it++) { int q = tid + it * 256; brow_[it] = q >> 2; bqi[it] = q & 3; }

#define ISSUE_CHUNK(c, s) {                                                       \
    uint32_t sa = sbase + (s) * SA_BYTES;                                         \
    uint32_t sb = sbase + 2 * SA_BYTES + (s) * SB_BYTES;                          \
    _Pragma("unroll")                                                             \
    for (int it = 0; it < 2; it++)                                                \
        CP_ASYNC16(sa + (uint32_t)(arow[it] * 80 + aqi[it] * 16),                 \
                   &g_U[(size_t)(i0 + arow[it]) * KSPL + (c) * KC + aqi[it] * 8]);\
    _Pragma("unroll")                                                             \
    for (int it = 0; it < 4; it++)                                                \
        CP_ASYNC16(sb + (uint32_t)(brow_[it] * 80 + bqi[it] * 16),                \
                   &g_V[(size_t)(j0 + brow_[it]) * KSPL + (c) * KC + bqi[it] * 8]);\
    CP_COMMIT(); }

    // ldmatrix lane offsets
    int a_m = (lane & 7) + ((lane >> 3) & 1) * 8;   // + warpM*64 + mf*16
    int a_k = ((lane >> 4) & 1) * 8;                // + ks*16
    int b_n = (lane & 7) + ((lane >> 4) & 1) * 8;   // + warpN*64 + nfp*16
    int b_k = ((lane >> 3) & 1) * 8;                // + ks*16

    ISSUE_CHUNK(0, 0);

#pragma unroll 1
    for (int c = 0; c < NCHUNK; c++) {
        int s = c & 1;
        if (c + 1 < NCHUNK) { ISSUE_CHUNK(c + 1, s ^ 1); CP_WAIT(1); }
        else                { CP_WAIT(0); }
        __syncthreads();

        uint32_t baseA = sbase + s * SA_BYTES;
        uint32_t baseB = sbase + 2 * SA_BYTES + s * SB_BYTES;
#pragma unroll
        for (int ks = 0; ks < 2; ks++) {
            uint32_t af[4][4], bf[4][4];
#pragma unroll
            for (int mf = 0; mf < 4; mf++) {
                int mm = warpM * 64 + mf * 16 + a_m;
                int kk = ks * 16 + a_k;
                ldsm_x4(af[mf][0], af[mf][1], af[mf][2], af[mf][3],
                        baseA + (uint32_t)(mm * SPAD + kk) * 2u);
            }
#pragma unroll
            for (int nfp = 0; nfp < 4; nfp++) {
                int nn = warpN * 64 + nfp * 16 + b_n;
                int kk = ks * 16 + b_k;
                ldsm_x4(bf[nfp][0], bf[nfp][1], bf[nfp][2], bf[nfp][3],
                        baseB + (uint32_t)(nn * SPAD + kk) * 2u);
            }
#pragma unroll
            for (int mf = 0; mf < 4; mf++)
#pragma unroll
                for (int nfp = 0; nfp < 4; nfp++) {
                    mma_fp16(acc[mf][2*nfp][0], acc[mf][2*nfp][1],
                             acc[mf][2*nfp][2], acc[mf][2*nfp][3],
                             af[mf][0], af[mf][1], af[mf][2], af[mf][3],
                             bf[nfp][0], bf[nfp][1]);
                    mma_fp16(acc[mf][2*nfp+1][0], acc[mf][2*nfp+1][1],
                             acc[mf][2*nfp+1][2], acc[mf][2*nfp+1][3],
                             af[mf][0], af[mf][1], af[mf][2], af[mf][3],
                             bf[nfp][2], bf[nfp][3]);
                }
        }
        __syncthreads();
    }

    // epilogue: x = acc + bias ; sigmoid with exact-underflow fast path
    float bias = *pb;
    int lr = lane >> 2, lc = (lane & 3) * 2;
#pragma unroll
    for (int mf = 0; mf < 4; mf++) {
#pragma unroll
        for (int nf = 0; nf < 8; nf++) {
            int i1 = i0 + warpM * 64 + mf * 16 + lr;
            int j = j0 + warpN * 64 + nf * 8 + lc;
#pragma unroll
            for (int half = 0; half < 2; half++) {
                int i = i1 + half * 8;
                float x0 = acc[mf][nf][half * 2 + 0] + bias;
                float x1 = acc[mf][nf][half * 2 + 1] + bias;
                float2 r;
                r.x = fast_sigmoid(x0);
                r.y = fast_sigmoid(x1);
                *reinterpret_cast<float2*>(&out[(size_t)i * NNODE + j]) = r;
            }
        }
    }
}

// ---------------- launch -----------------------------------------------------
extern "C" void kernel_launch(void* const* d_in, const int* in_sizes, int n_in,
                              void* d_out, int out_size) {
    const float* z     = (const float*)d_in[0];
    const float* gamma = (const float*)d_in[1];
    const float* delta = (const float*)d_in[2];
    const float* Wz    = (const float*)d_in[3];
    const float* Wg    = (const float*)d_in[4];
    const float* Wd    = (const float*)d_in[5];
    const float* pb    = (const float*)d_in[6];
    const float* pwg   = (const float*)d_in[7];
    const float* pwd   = (const float*)d_in[8];
    float* out = (float*)d_out;

    cudaFuncSetAttribute(pair_kernel, cudaFuncAttributeMaxDynamicSharedMemorySize,
                         SMEM_PAIR_TOTAL);

    softmax_cols<<<384, 128>>>(Wz, Wg, Wd);
    gemm_small<<<dim3(NNODE / 64, 3), 256>>>(z, gamma, delta, out);
    prep_split<<<NNODE, 128>>>(pwg, pwd);
    pair_kernel<<<2048, 256, SMEM_PAIR_TOTAL>>>(out, pb);
}

// round 10
// speedup vs baseline: 1.0064x; 1.0064x over previous
#include <cuda_runtime.h>
#include <cuda_fp16.h>
#include <cstdint>
#include <math.h>

#define NNODE 8192
#define DIN   512
#define DLAT  128
#define NSLOT 16               // fp16 split slots per latent k
#define KSPL  (DLAT * NSLOT)   // 2048

static const int OUT_NN = NNODE * NNODE;           // 67108864
static const int OUT_NL = NNODE * DLAT;            // 1048576

// ---------------- scratch (device globals; no allocation allowed) ----------
__device__ float g_T[3][DIN][DLAT];                // softmaxed transforms
__device__ float g_zd[NNODE * DLAT];
__device__ float g_ig[NNODE * DLAT];               // 1/(gd+SMALL)
__device__ float g_id[NNODE * DLAT];               // 1/(dd+SMALL)
__device__ __half g_U[(size_t)NNODE * KSPL];       // split-U (32 MB)
__device__ __half g_V[(size_t)NNODE * KSPL];       // split-V (32 MB)

// ---------------- K1: column softmax of the three W matrices ---------------
__global__ void softmax_cols(const float* __restrict__ Wz,
                             const float* __restrict__ Wg,
                             const float* __restrict__ Wd) {
    int mat = blockIdx.x >> 7;        // 0..2
    int col = blockIdx.x & 127;
    const float* W = (mat == 0) ? Wz : (mat == 1) ? Wg : Wd;
    int t = threadIdx.x;              // 128 threads
    __shared__ float red[128];

    float v[4];
#pragma unroll
    for (int r = 0; r < 4; r++) v[r] = W[(t + r * 128) * DLAT + col];

    float m = fmaxf(fmaxf(v[0], v[1]), fmaxf(v[2], v[3]));
    red[t] = m; __syncthreads();
    for (int s = 64; s > 0; s >>= 1) {
        if (t < s) red[t] = fmaxf(red[t], red[t + s]);
        __syncthreads();
    }
    m = red[0]; __syncthreads();

    float e[4], sum = 0.f;
#pragma unroll
    for (int r = 0; r < 4; r++) { e[r] = expf(v[r] - m); sum += e[r]; }
    red[t] = sum; __syncthreads();
    for (int s = 64; s > 0; s >>= 1) {
        if (t < s) red[t] += red[t + s];
        __syncthreads();
    }
    float inv = 1.f / red[0];
#pragma unroll
    for (int r = 0; r < 4; r++) g_T[mat][t + r * 128][col] = e[r] * inv;
}

// ---------------- K2a: zd / gd / dd GEMMs (fp32 SIMT) ----------------------
__global__ __launch_bounds__(256) void gemm_small(const float* __restrict__ z,
                                                  const float* __restrict__ gamma,
                                                  const float* __restrict__ delta,
                                                  float* __restrict__ out) {
    __shared__ float As[32][65];      // [k][m] transposed
    __shared__ float Bs[32][128];

    int which = blockIdx.y;
    const float* A = (which == 0) ? z : (which == 1) ? gamma : delta;
    const float* B = &g_T[which][0][0];
    int r0 = blockIdx.x * 64;

    int tid = threadIdx.x;
    int ty = tid >> 4, tx = tid & 15;

    float acc[4][8];
#pragma unroll
    for (int i = 0; i < 4; i++)
#pragma unroll
        for (int j = 0; j < 8; j++) acc[i][j] = 0.f;

    for (int kc = 0; kc < DIN / 32; kc++) {
#pragma unroll
        for (int it = 0; it < 2; it++) {
            int linear = tid + it * 256;          // 0..511
            int arow = linear >> 3, ac4 = linear & 7;
            float4 va = *reinterpret_cast<const float4*>(
                &A[(r0 + arow) * DIN + kc * 32 + ac4 * 4]);
            As[ac4 * 4 + 0][arow] = va.x;
            As[ac4 * 4 + 1][arow] = va.y;
            As[ac4 * 4 + 2][arow] = va.z;
            As[ac4 * 4 + 3][arow] = va.w;
        }
#pragma unroll
        for (int it = 0; it < 4; it++) {
            int linear = tid + it * 256;          // 0..1023
            int brow = linear >> 5, bc4 = linear & 31;
            *reinterpret_cast<float4*>(&Bs[brow][bc4 * 4]) =
                *reinterpret_cast<const float4*>(&B[(kc * 32 + brow) * DLAT + bc4 * 4]);
        }
        __syncthreads();

#pragma unroll
        for (int kk = 0; kk < 32; kk++) {
            float a[4];
#pragma unroll
            for (int i = 0; i < 4; i++) a[i] = As[kk][ty * 4 + i];
            float4 b0 = *reinterpret_cast<float4*>(&Bs[kk][tx * 4]);
            float4 b1 = *reinterpret_cast<float4*>(&Bs[kk][64 + tx * 4]);
#pragma unroll
            for (int i = 0; i < 4; i++) {
                acc[i][0] = fmaf(a[i], b0.x, acc[i][0]);
                acc[i][1] = fmaf(a[i], b0.y, acc[i][1]);
                acc[i][2] = fmaf(a[i], b0.z, acc[i][2]);
                acc[i][3] = fmaf(a[i], b0.w, acc[i][3]);
                acc[i][4] = fmaf(a[i], b1.x, acc[i][4]);
                acc[i][5] = fmaf(a[i], b1.y, acc[i][5]);
                acc[i][6] = fmaf(a[i], b1.z, acc[i][6]);
                acc[i][7] = fmaf(a[i], b1.w, acc[i][7]);
            }
        }
        __syncthreads();
    }

#pragma unroll
    for (int i = 0; i < 4; i++) {
        int node = r0 + ty * 4 + i;
#pragma unroll
        for (int j = 0; j < 8; j++) {
            int col = (j < 4) ? (tx * 4 + j) : (64 + tx * 4 + (j - 4));
            int idx = node * DLAT + col;
            float v = acc[i][j];
            if (which == 0) {
                g_zd[idx] = v;
                out[OUT_NN + idx] = v;
            } else if (which == 1) {
                out[OUT_NN + OUT_NL + idx] = v;
                g_ig[idx] = 1.f / (v + 1e-16f);
            } else {
                out[OUT_NN + 2 * OUT_NL + idx] = v;
                g_id[idx] = 1.f / (v + 1e-16f);
            }
        }
    }
}

// ---------------- K2b: build telescoped fp16-split U, V ---------------------
__device__ __forceinline__ void split2(float x, float& h, float& l) {
    h = __half2float(__float2half_rn(x));
    l = x - h;
}

__global__ __launch_bounds__(128) void prep_split(const float* __restrict__ pwg,
                                                  const float* __restrict__ pwd) {
    int i = blockIdx.x;
    int k = threadIdx.x;          // 0..127
    float zd = g_zd[i * DLAT + k];
    float ig = g_ig[i * DLAT + k];
    float id = g_id[i * DLAT + k];
    float z2 = zd * zd;
    float wgn = (*pwg) * 8192.0f;
    float wdn = (*pwd) * 8192.0f;

    float u1 = -(wgn * ig * z2);      // pairs with v=1
    float v6 = wdn * z2 * id;         // pairs with u=-1
    float U2 = (2.f * wgn * ig * zd) * 0.03125f;
    float V2 = zd * 32.f;
    float U3 = -(wgn * ig) * 0.0078125f;
    float V3 = z2 * 128.f;
    float U4 = -z2 * 128.f;
    float V4 = (wdn * id) * 0.0078125f;
    float U5 = (2.f * zd) * 16.f;
    float V5 = (wdn * zd * id) * 0.0625f;

    const float S  = 256.f;
    const float SI = 0.00390625f;

    float us[NSLOT], vs[NSLOT];
    float h, l;

    split2(u1, h, l);
    us[0] = h;       vs[0] = 1.f;
    us[1] = l * S;   vs[1] = SI;

#define PG(b, U, V) { float uh, ul, vh, vl; split2(U, uh, ul); split2(V, vh, vl); \
    us[(b)+0] = uh;      vs[(b)+0] = vh;       \
    us[(b)+1] = uh * SI; vs[(b)+1] = vl * S;   \
    us[(b)+2] = ul * S;  vs[(b)+2] = vh * SI; }

    PG(2,  U2, V2)
    PG(5,  U3, V3)
    PG(8,  U4, V4)
    PG(11, U5, V5)
#undef PG

    split2(v6, h, l);
    us[14] = -1.f;  vs[14] = h;
    us[15] = -SI;   vs[15] = l * S;

    __half hu[NSLOT], hv[NSLOT];
#pragma unroll
    for (int s = 0; s < NSLOT; s++) {
        hu[s] = __float2half_rn(us[s]);
        hv[s] = __float2half_rn(vs[s]);
    }
    size_t base = (size_t)i * KSPL + (size_t)k * NSLOT;
    *reinterpret_cast<uint4*>(&g_U[base])     = *reinterpret_cast<uint4*>(&hu[0]);
    *reinterpret_cast<uint4*>(&g_U[base + 8]) = *reinterpret_cast<uint4*>(&hu[8]);
    *reinterpret_cast<uint4*>(&g_V[base])     = *reinterpret_cast<uint4*>(&hv[0]);
    *reinterpret_cast<uint4*>(&g_V[base + 8]) = *reinterpret_cast<uint4*>(&hv[8]);
}

// ---------------- K3: 8192x8192x2048 fp16 mma.sync GEMM --------------------
// Block tile 128x256, warp grid 2x4, warp tile 64x64 (4x8 m16n8 frags).
// 4-stage cp.async ring, ONE __syncthreads per K=32 chunk, issue-ahead.
__device__ __forceinline__ uint32_t smem_u32(const void* p) {
    uint32_t a;
    asm("{ .reg .u64 t; cvta.to.shared.u64 t, %1; cvt.u32.u64 %0, t; }"
        : "=r"(a) : "l"(p));
    return a;
}
__device__ __forceinline__ void ldsm_x4(uint32_t& r0, uint32_t& r1,
                                        uint32_t& r2, uint32_t& r3, uint32_t addr) {
    asm volatile("ldmatrix.sync.aligned.m8n8.x4.shared.b16 {%0,%1,%2,%3}, [%4];\n"
                 : "=r"(r0), "=r"(r1), "=r"(r2), "=r"(r3) : "r"(addr));
}
__device__ __forceinline__ void mma_fp16(float& c0, float& c1, float& c2, float& c3,
                                         uint32_t a0, uint32_t a1, uint32_t a2, uint32_t a3,
                                         uint32_t b0, uint32_t b1) {
    asm volatile("mma.sync.aligned.m16n8k16.row.col.f32.f16.f16.f32 "
                 "{%0,%1,%2,%3}, {%4,%5,%6,%7}, {%8,%9}, {%0,%1,%2,%3};\n"
                 : "+f"(c0), "+f"(c1), "+f"(c2), "+f"(c3)
                 : "r"(a0), "r"(a1), "r"(a2), "r"(a3), "r"(b0), "r"(b1));
}
#define CP_ASYNC16(sm, gm) \
    asm volatile("cp.async.cg.shared.global [%0], [%1], 16;\n" :: "r"(sm), "l"(gm))
#define CP_COMMIT() asm volatile("cp.async.commit_group;\n" ::: "memory")
#define CP_WAIT(n)  asm volatile("cp.async.wait_group %0;\n" :: "n"(n) : "memory")

__device__ __forceinline__ float fast_sigmoid(float x) {
    if (x < -88.f) return 0.f;
    return 1.f / (1.f + expf(-x));
}

#define SPAD   40                 // halves per smem row (80 B; 20-bank shift)
#define TM     128
#define TN     256
#define KC     32
#define NCHUNK (KSPL / KC)        // 64
#define STAGES 4
#define SA_BYTES (TM * SPAD * 2)  // 10240
#define SB_BYTES (TN * SPAD * 2)  // 20480
#define STAGE_BYTES (SA_BYTES + SB_BYTES)               // 30720
#define SMEM_PAIR_TOTAL (STAGES * STAGE_BYTES)          // 122880

__global__ __launch_bounds__(256, 1) void pair_kernel(float* __restrict__ out,
                                                      const float* __restrict__ pb) {
    extern __shared__ __align__(128) char smem[];
    uint32_t sbase = smem_u32(smem);

    int tid = threadIdx.x;
    int lane = tid & 31, wid = tid >> 5;
    int warpM = wid >> 2, warpN = wid & 3;   // 2 x 4 warps; warp tile 64x64

    // tile swizzle: groups of 8 brows x 32 bcols keep wave working set in L2
    int bx = blockIdx.x;                     // 0..2047 (64 brows x 32 bcols)
    int brow = ((bx >> 8) << 3) + ((bx & 255) >> 5);
    int bcol = bx & 31;
    int i0 = brow * TM, j0 = bcol * TN;

    float acc[4][8][4];
#pragma unroll
    for (int a = 0; a < 4; a++)
#pragma unroll
        for (int b = 0; b < 8; b++)
#pragma unroll
            for (int c = 0; c < 4; c++) acc[a][b][c] = 0.f;

    // cp.async lane mapping: quad index q -> row = q>>2, qi = q&3 (16B each)
    int arow[2], aqi[2], brow_[4], bqi[4];
#pragma unroll
    for (int it = 0; it < 2; it++) { int q = tid + it * 256; arow[it] = q >> 2; aqi[it] = q & 3; }
#pragma unroll
    for (int it = 0; it < 4; it++) { int q = tid + it * 256; brow_[it] = q >> 2; bqi[it] = q & 3; }

#define ISSUE_CHUNK(c, s) {                                                       \
    uint32_t sa = sbase + (s) * STAGE_BYTES;                                      \
    uint32_t sb = sa + SA_BYTES;                                                  \
    _Pragma("unroll")                                                             \
    for (int it = 0; it < 2; it++)                                                \
        CP_ASYNC16(sa + (uint32_t)(arow[it] * 80 + aqi[it] * 16),                 \
                   &g_U[(size_t)(i0 + arow[it]) * KSPL + (c) * KC + aqi[it] * 8]);\
    _Pragma("unroll")                                                             \
    for (int it = 0; it < 4; it++)                                                \
        CP_ASYNC16(sb + (uint32_t)(brow_[it] * 80 + bqi[it] * 16),                \
                   &g_V[(size_t)(j0 + brow_[it]) * KSPL + (c) * KC + bqi[it] * 8]);\
    CP_COMMIT(); }

    // ldmatrix lane offsets
    int a_m = (lane & 7) + ((lane >> 3) & 1) * 8;   // + warpM*64 + mf*16
    int a_k = ((lane >> 4) & 1) * 8;                // + ks*16
    int b_n = (lane & 7) + ((lane >> 4) & 1) * 8;   // + warpN*64 + nfp*16
    int b_k = ((lane >> 3) & 1) * 8;                // + ks*16

    // prologue: fill STAGES-1 stages
    ISSUE_CHUNK(0, 0);
    ISSUE_CHUNK(1, 1);
    ISSUE_CHUNK(2, 2);

#pragma unroll 1
    for (int c = 0; c < NCHUNK; c++) {
        int st = c & (STAGES - 1);
        CP_WAIT(STAGES - 2);          // chunk c resident
        __syncthreads();              // all warps done with buffer (c-1)

        // issue-ahead into the buffer freed last iteration; empty commit keeps
        // the group-count invariant so CP_WAIT(2) always means "chunk c ready"
        if (c + STAGES - 1 < NCHUNK) { ISSUE_CHUNK(c + STAGES - 1, (c + STAGES - 1) & (STAGES - 1)); }
        else                         { CP_COMMIT(); }

        uint32_t baseA = sbase + st * STAGE_BYTES;
        uint32_t baseB = baseA + SA_BYTES;
#pragma unroll
        for (int ks = 0; ks < 2; ks++) {
            uint32_t af[4][4], bf[4][4];
#pragma unroll
            for (int mf = 0; mf < 4; mf++) {
                int mm = warpM * 64 + mf * 16 + a_m;
                int kk = ks * 16 + a_k;
                ldsm_x4(af[mf][0], af[mf][1], af[mf][2], af[mf][3],
                        baseA + (uint32_t)(mm * SPAD + kk) * 2u);
            }
#pragma unroll
            for (int nfp = 0; nfp < 4; nfp++) {
                int nn = warpN * 64 + nfp * 16 + b_n;
                int kk = ks * 16 + b_k;
                ldsm_x4(bf[nfp][0], bf[nfp][1], bf[nfp][2], bf[nfp][3],
                        baseB + (uint32_t)(nn * SPAD + kk) * 2u);
            }
#pragma unroll
            for (int mf = 0; mf < 4; mf++)
#pragma unroll
                for (int nfp = 0; nfp < 4; nfp++) {
                    mma_fp16(acc[mf][2*nfp][0], acc[mf][2*nfp][1],
                             acc[mf][2*nfp][2], acc[mf][2*nfp][3],
                             af[mf][0], af[mf][1], af[mf][2], af[mf][3],
                             bf[nfp][0], bf[nfp][1]);
                    mma_fp16(acc[mf][2*nfp+1][0], acc[mf][2*nfp+1][1],
                             acc[mf][2*nfp+1][2], acc[mf][2*nfp+1][3],
                             af[mf][0], af[mf][1], af[mf][2], af[mf][3],
                             bf[nfp][2], bf[nfp][3]);
                }
        }
    }

    // epilogue: x = acc + bias ; sigmoid with exact-underflow fast path
    float bias = *pb;
    int lr = lane >> 2, lc = (lane & 3) * 2;
#pragma unroll
    for (int mf = 0; mf < 4; mf++) {
#pragma unroll
        for (int nf = 0; nf < 8; nf++) {
            int i1 = i0 + warpM * 64 + mf * 16 + lr;
            int j = j0 + warpN * 64 + nf * 8 + lc;
#pragma unroll
            for (int half = 0; half < 2; half++) {
                int i = i1 + half * 8;
                float x0 = acc[mf][nf][half * 2 + 0] + bias;
                float x1 = acc[mf][nf][half * 2 + 1] + bias;
                float2 r;
                r.x = fast_sigmoid(x0);
                r.y = fast_sigmoid(x1);
                *reinterpret_cast<float2*>(&out[(size_t)i * NNODE + j]) = r;
            }
        }
    }
}

// ---------------- launch -----------------------------------------------------
extern "C" void kernel_launch(void* const* d_in, const int* in_sizes, int n_in,
                              void* d_out, int out_size) {
    const float* z     = (const float*)d_in[0];
    const float* gamma = (const float*)d_in[1];
    const float* delta = (const float*)d_in[2];
    const float* Wz    = (const float*)d_in[3];
    const float* Wg    = (const float*)d_in[4];
    const float* Wd    = (const float*)d_in[5];
    const float* pb    = (const float*)d_in[6];
    const float* pwg   = (const float*)d_in[7];
    const float* pwd   = (const float*)d_in[8];
    float* out = (float*)d_out;

    cudaFuncSetAttribute(pair_kernel, cudaFuncAttributeMaxDynamicSharedMemorySize,
                         SMEM_PAIR_TOTAL);

    softmax_cols<<<384, 128>>>(Wz, Wg, Wd);
    gemm_small<<<dim3(NNODE / 64, 3), 256>>>(z, gamma, delta, out);
    prep_split<<<NNODE, 128>>>(pwg, pwd);
    pair_kernel<<<2048, 256, SMEM_PAIR_TOTAL>>>(out, pb);
}

// round 12
// speedup vs baseline: 1.1848x; 1.1772x over previous
#include <cuda_runtime.h>
#include <cuda_fp16.h>
#include <cstdint>
#include <math.h>

#define NNODE 8192
#define DIN   512
#define DLAT  128
#define NSLOT 16               // fp16 split slots per latent k
#define KSPL  (DLAT * NSLOT)   // 2048

static const int OUT_NN = NNODE * NNODE;           // 67108864
static const int OUT_NL = NNODE * DLAT;            // 1048576

// ---------------- scratch (device globals; no allocation allowed) ----------
__device__ float g_T[3][DIN][DLAT];                // softmaxed transforms
__device__ float g_zd[NNODE * DLAT];
__device__ float g_ig[NNODE * DLAT];               // 1/(gd+SMALL)
__device__ float g_id[NNODE * DLAT];               // 1/(dd+SMALL)
__device__ __half g_U[(size_t)NNODE * KSPL];       // split-U (32 MB)
__device__ __half g_V[(size_t)NNODE * KSPL];       // split-V (32 MB)

// ---------------- K1: column softmax of the three W matrices ---------------
__global__ void softmax_cols(const float* __restrict__ Wz,
                             const float* __restrict__ Wg,
                             const float* __restrict__ Wd) {
    int mat = blockIdx.x >> 7;        // 0..2
    int col = blockIdx.x & 127;
    const float* W = (mat == 0) ? Wz : (mat == 1) ? Wg : Wd;
    int t = threadIdx.x;              // 128 threads
    __shared__ float red[128];

    float v[4];
#pragma unroll
    for (int r = 0; r < 4; r++) v[r] = W[(t + r * 128) * DLAT + col];

    float m = fmaxf(fmaxf(v[0], v[1]), fmaxf(v[2], v[3]));
    red[t] = m; __syncthreads();
    for (int s = 64; s > 0; s >>= 1) {
        if (t < s) red[t] = fmaxf(red[t], red[t + s]);
        __syncthreads();
    }
    m = red[0]; __syncthreads();

    float e[4], sum = 0.f;
#pragma unroll
    for (int r = 0; r < 4; r++) { e[r] = expf(v[r] - m); sum += e[r]; }
    red[t] = sum; __syncthreads();
    for (int s = 64; s > 0; s >>= 1) {
        if (t < s) red[t] += red[t + s];
        __syncthreads();
    }
    float inv = 1.f / red[0];
#pragma unroll
    for (int r = 0; r < 4; r++) g_T[mat][t + r * 128][col] = e[r] * inv;
}

// ---------------- K2a: zd / gd / dd GEMMs (fp32 SIMT) ----------------------
__global__ __launch_bounds__(256) void gemm_small(const float* __restrict__ z,
                                                  const float* __restrict__ gamma,
                                                  const float* __restrict__ delta,
                                                  float* __restrict__ out) {
    __shared__ float As[32][65];      // [k][m] transposed
    __shared__ float Bs[32][128];

    int which = blockIdx.y;
    const float* A = (which == 0) ? z : (which == 1) ? gamma : delta;
    const float* B = &g_T[which][0][0];
    int r0 = blockIdx.x * 64;

    int tid = threadIdx.x;
    int ty = tid >> 4, tx = tid & 15;

    float acc[4][8];
#pragma unroll
    for (int i = 0; i < 4; i++)
#pragma unroll
        for (int j = 0; j < 8; j++) acc[i][j] = 0.f;

    for (int kc = 0; kc < DIN / 32; kc++) {
#pragma unroll
        for (int it = 0; it < 2; it++) {
            int linear = tid + it * 256;          // 0..511
            int arow = linear >> 3, ac4 = linear & 7;
            float4 va = *reinterpret_cast<const float4*>(
                &A[(r0 + arow) * DIN + kc * 32 + ac4 * 4]);
            As[ac4 * 4 + 0][arow] = va.x;
            As[ac4 * 4 + 1][arow] = va.y;
            As[ac4 * 4 + 2][arow] = va.z;
            As[ac4 * 4 + 3][arow] = va.w;
        }
#pragma unroll
        for (int it = 0; it < 4; it++) {
            int linear = tid + it * 256;          // 0..1023
            int brow = linear >> 5, bc4 = linear & 31;
            *reinterpret_cast<float4*>(&Bs[brow][bc4 * 4]) =
                *reinterpret_cast<const float4*>(&B[(kc * 32 + brow) * DLAT + bc4 * 4]);
        }
        __syncthreads();

#pragma unroll
        for (int kk = 0; kk < 32; kk++) {
            float a[4];
#pragma unroll
            for (int i = 0; i < 4; i++) a[i] = As[kk][ty * 4 + i];
            float4 b0 = *reinterpret_cast<float4*>(&Bs[kk][tx * 4]);
            float4 b1 = *reinterpret_cast<float4*>(&Bs[kk][64 + tx * 4]);
#pragma unroll
            for (int i = 0; i < 4; i++) {
                acc[i][0] = fmaf(a[i], b0.x, acc[i][0]);
                acc[i][1] = fmaf(a[i], b0.y, acc[i][1]);
                acc[i][2] = fmaf(a[i], b0.z, acc[i][2]);
                acc[i][3] = fmaf(a[i], b0.w, acc[i][3]);
                acc[i][4] = fmaf(a[i], b1.x, acc[i][4]);
                acc[i][5] = fmaf(a[i], b1.y, acc[i][5]);
                acc[i][6] = fmaf(a[i], b1.z, acc[i][6]);
                acc[i][7] = fmaf(a[i], b1.w, acc[i][7]);
            }
        }
        __syncthreads();
    }

#pragma unroll
    for (int i = 0; i < 4; i++) {
        int node = r0 + ty * 4 + i;
#pragma unroll
        for (int j = 0; j < 8; j++) {
            int col = (j < 4) ? (tx * 4 + j) : (64 + tx * 4 + (j - 4));
            int idx = node * DLAT + col;
            float v = acc[i][j];
            if (which == 0) {
                g_zd[idx] = v;
                out[OUT_NN + idx] = v;
            } else if (which == 1) {
                out[OUT_NN + OUT_NL + idx] = v;
                g_ig[idx] = 1.f / (v + 1e-16f);
            } else {
                out[OUT_NN + 2 * OUT_NL + idx] = v;
                g_id[idx] = 1.f / (v + 1e-16f);
            }
        }
    }
}

// ---------------- K2b: build telescoped fp16-split U, V ---------------------
__device__ __forceinline__ void split2(float x, float& h, float& l) {
    h = __half2float(__float2half_rn(x));
    l = x - h;
}

__global__ __launch_bounds__(128) void prep_split(const float* __restrict__ pwg,
                                                  const float* __restrict__ pwd) {
    int i = blockIdx.x;
    int k = threadIdx.x;          // 0..127
    float zd = g_zd[i * DLAT + k];
    float ig = g_ig[i * DLAT + k];
    float id = g_id[i * DLAT + k];
    float z2 = zd * zd;
    float wgn = (*pwg) * 8192.0f;
    float wdn = (*pwd) * 8192.0f;

    float u1 = -(wgn * ig * z2);      // pairs with v=1
    float v6 = wdn * z2 * id;         // pairs with u=-1
    float U2 = (2.f * wgn * ig * zd) * 0.03125f;
    float V2 = zd * 32.f;
    float U3 = -(wgn * ig) * 0.0078125f;
    float V3 = z2 * 128.f;
    float U4 = -z2 * 128.f;
    float V4 = (wdn * id) * 0.0078125f;
    float U5 = (2.f * zd) * 16.f;
    float V5 = (wdn * zd * id) * 0.0625f;

    const float S  = 256.f;
    const float SI = 0.00390625f;

    float us[NSLOT], vs[NSLOT];
    float h, l;

    split2(u1, h, l);
    us[0] = h;       vs[0] = 1.f;
    us[1] = l * S;   vs[1] = SI;

#define PG(b, U, V) { float uh, ul, vh, vl; split2(U, uh, ul); split2(V, vh, vl); \
    us[(b)+0] = uh;      vs[(b)+0] = vh;       \
    us[(b)+1] = uh * SI; vs[(b)+1] = vl * S;   \
    us[(b)+2] = ul * S;  vs[(b)+2] = vh * SI; }

    PG(2,  U2, V2)
    PG(5,  U3, V3)
    PG(8,  U4, V4)
    PG(11, U5, V5)
#undef PG

    split2(v6, h, l);
    us[14] = -1.f;  vs[14] = h;
    us[15] = -SI;   vs[15] = l * S;

    __half hu[NSLOT], hv[NSLOT];
#pragma unroll
    for (int s = 0; s < NSLOT; s++) {
        hu[s] = __float2half_rn(us[s]);
        hv[s] = __float2half_rn(vs[s]);
    }
    size_t base = (size_t)i * KSPL + (size_t)k * NSLOT;
    *reinterpret_cast<uint4*>(&g_U[base])     = *reinterpret_cast<uint4*>(&hu[0]);
    *reinterpret_cast<uint4*>(&g_U[base + 8]) = *reinterpret_cast<uint4*>(&hu[8]);
    *reinterpret_cast<uint4*>(&g_V[base])     = *reinterpret_cast<uint4*>(&hv[0]);
    *reinterpret_cast<uint4*>(&g_V[base + 8]) = *reinterpret_cast<uint4*>(&hv[8]);
}

// ---------------- K3: 8192x8192x2048 fp16 mma.sync GEMM --------------------
// Block tile 128x128, warp grid 2x4, warp tile 64x32 (4x4 m16n8 frags).
// 2 CTAs/SM (regs capped), 4-stage cp.async ring, ldsm_x4 for both A and B.
__device__ __forceinline__ uint32_t smem_u32(const void* p) {
    uint32_t a;
    asm("{ .reg .u64 t; cvta.to.shared.u64 t, %1; cvt.u32.u64 %0, t; }"
        : "=r"(a) : "l"(p));
    return a;
}
__device__ __forceinline__ void ldsm_x4(uint32_t& r0, uint32_t& r1,
                                        uint32_t& r2, uint32_t& r3, uint32_t addr) {
    asm volatile("ldmatrix.sync.aligned.m8n8.x4.shared.b16 {%0,%1,%2,%3}, [%4];\n"
                 : "=r"(r0), "=r"(r1), "=r"(r2), "=r"(r3) : "r"(addr));
}
__device__ __forceinline__ void mma_fp16(float& c0, float& c1, float& c2, float& c3,
                                         uint32_t a0, uint32_t a1, uint32_t a2, uint32_t a3,
                                         uint32_t b0, uint32_t b1) {
    asm volatile("mma.sync.aligned.m16n8k16.row.col.f32.f16.f16.f32 "
                 "{%0,%1,%2,%3}, {%4,%5,%6,%7}, {%8,%9}, {%0,%1,%2,%3};\n"
                 : "+f"(c0), "+f"(c1), "+f"(c2), "+f"(c3)
                 : "r"(a0), "r"(a1), "r"(a2), "r"(a3), "r"(b0), "r"(b1));
}
#define CP_ASYNC16(sm, gm) \
    asm volatile("cp.async.cg.shared.global [%0], [%1], 16;\n" :: "r"(sm), "l"(gm))
#define CP_COMMIT() asm volatile("cp.async.commit_group;\n" ::: "memory")
#define CP_WAIT(n)  asm volatile("cp.async.wait_group %0;\n" :: "n"(n) : "memory")

__device__ __forceinline__ float fast_sigmoid(float x) {
    if (x < -88.f) return 0.f;
    return 1.f / (1.f + expf(-x));
}

#define SPAD   40                 // halves per smem row (80 B; 20-bank shift)
#define TM     128
#define TN     128
#define KC     32
#define NCHUNK (KSPL / KC)        // 64
#define STAGES 4
#define SA_BYTES (TM * SPAD * 2)  // 10240
#define SB_BYTES (TN * SPAD * 2)  // 10240
#define STAGE_BYTES (SA_BYTES + SB_BYTES)               // 20480
#define SMEM_PAIR_TOTAL (STAGES * STAGE_BYTES)          // 81920

__global__ __launch_bounds__(256, 2) void pair_kernel(float* __restrict__ out,
                                                      const float* __restrict__ pb) {
    extern __shared__ __align__(128) char smem[];
    uint32_t sbase = smem_u32(smem);

    int tid = threadIdx.x;
    int lane = tid & 31, wid = tid >> 5;
    int warpM = wid >> 2, warpN = wid & 3;   // 2 x 4 warps; warp tile 64x32

    // tile swizzle: groups of 16 brows x 64 bcols keep wave working set in L2
    int bx = blockIdx.x;                     // 0..4095 (64 brows x 64 bcols)
    int brow = ((bx >> 10) << 4) + ((bx & 1023) >> 6);
    int bcol = bx & 63;
    int i0 = brow * TM, j0 = bcol * TN;

    float acc[4][4][4];
#pragma unroll
    for (int a = 0; a < 4; a++)
#pragma unroll
        for (int b = 0; b < 4; b++)
#pragma unroll
            for (int c = 0; c < 4; c++) acc[a][b][c] = 0.f;

    // cp.async lane mapping: quad q -> row = q>>2 (4x16B per 64B row), qi = q&3
    int arow[2], aqi[2];
#pragma unroll
    for (int it = 0; it < 2; it++) { int q = tid + it * 256; arow[it] = q >> 2; aqi[it] = q & 3; }

#define ISSUE_CHUNK(c, s) {                                                       \
    uint32_t sa = sbase + (s) * STAGE_BYTES;                                      \
    uint32_t sb = sa + SA_BYTES;                                                  \
    _Pragma("unroll")                                                             \
    for (int it = 0; it < 2; it++)                                                \
        CP_ASYNC16(sa + (uint32_t)(arow[it] * 80 + aqi[it] * 16),                 \
                   &g_U[(size_t)(i0 + arow[it]) * KSPL + (c) * KC + aqi[it] * 8]);\
    _Pragma("unroll")                                                             \
    for (int it = 0; it < 2; it++)                                                \
        CP_ASYNC16(sb + (uint32_t)(arow[it] * 80 + aqi[it] * 16),                 \
                   &g_V[(size_t)(j0 + arow[it]) * KSPL + (c) * KC + aqi[it] * 8]);\
    CP_COMMIT(); }

    // ldmatrix lane offsets (x4 layout for both A and B)
    int a_m = (lane & 7) + ((lane >> 3) & 1) * 8;   // + warpM*64 + mf*16
    int a_k = ((lane >> 4) & 1) * 8;                // + ks*16
    int b_n = (lane & 7) + ((lane >> 4) & 1) * 8;   // + warpN*32 + nfp*16
    int b_k = ((lane >> 3) & 1) * 8;                // + ks*16

    // prologue: fill STAGES-1 stages
    ISSUE_CHUNK(0, 0);
    ISSUE_CHUNK(1, 1);
    ISSUE_CHUNK(2, 2);

#pragma unroll 1
    for (int c = 0; c < NCHUNK; c++) {
        int st = c & (STAGES - 1);
        CP_WAIT(STAGES - 2);          // chunk c resident
        __syncthreads();              // all warps done with the recycled buffer

        if (c + STAGES - 1 < NCHUNK) { ISSUE_CHUNK(c + STAGES - 1, (c + STAGES - 1) & (STAGES - 1)); }
        else                         { CP_COMMIT(); }

        uint32_t baseA = sbase + st * STAGE_BYTES;
        uint32_t baseB = baseA + SA_BYTES;
#pragma unroll
        for (int ks = 0; ks < 2; ks++) {
            uint32_t af[4][4], bf[2][4];
#pragma unroll
            for (int mf = 0; mf < 4; mf++) {
                int mm = warpM * 64 + mf * 16 + a_m;
                int kk = ks * 16 + a_k;
                ldsm_x4(af[mf][0], af[mf][1], af[mf][2], af[mf][3],
                        baseA + (uint32_t)(mm * SPAD + kk) * 2u);
            }
#pragma unroll
            for (int nfp = 0; nfp < 2; nfp++) {
                int nn = warpN * 32 + nfp * 16 + b_n;
                int kk = ks * 16 + b_k;
                ldsm_x4(bf[nfp][0], bf[nfp][1], bf[nfp][2], bf[nfp][3],
                        baseB + (uint32_t)(nn * SPAD + kk) * 2u);
            }
#pragma unroll
            for (int mf = 0; mf < 4; mf++)
#pragma unroll
                for (int nfp = 0; nfp < 2; nfp++) {
                    mma_fp16(acc[mf][2*nfp][0], acc[mf][2*nfp][1],
                             acc[mf][2*nfp][2], acc[mf][2*nfp][3],
                             af[mf][0], af[mf][1], af[mf][2], af[mf][3],
                             bf[nfp][0], bf[nfp][1]);
                    mma_fp16(acc[mf][2*nfp+1][0], acc[mf][2*nfp+1][1],
                             acc[mf][2*nfp+1][2], acc[mf][2*nfp+1][3],
                             af[mf][0], af[mf][1], af[mf][2], af[mf][3],
                             bf[nfp][2], bf[nfp][3]);
                }
        }
    }

    // epilogue: x = acc + bias ; sigmoid with exact-underflow fast path
    float bias = *pb;
    int lr = lane >> 2, lc = (lane & 3) * 2;
#pragma unroll
    for (int mf = 0; mf < 4; mf++) {
#pragma unroll
        for (int nf = 0; nf < 4; nf++) {
            int i1 = i0 + warpM * 64 + mf * 16 + lr;
            int j = j0 + warpN * 32 + (nf >> 1) * 16 + (nf & 1) * 8 + lc;
#pragma unroll
            for (int half = 0; half < 2; half++) {
                int i = i1 + half * 8;
                float x0 = acc[mf][nf][half * 2 + 0] + bias;
                float x1 = acc[mf][nf][half * 2 + 1] + bias;
                float2 r;
                r.x = fast_sigmoid(x0);
                r.y = fast_sigmoid(x1);
                *reinterpret_cast<float2*>(&out[(size_t)i * NNODE + j]) = r;
            }
        }
    }
}

// ---------------- launch -----------------------------------------------------
extern "C" void kernel_launch(void* const* d_in, const int* in_sizes, int n_in,
                              void* d_out, int out_size) {
    const float* z     = (const float*)d_in[0];
    const float* gamma = (const float*)d_in[1];
    const float* delta = (const float*)d_in[2];
    const float* Wz    = (const float*)d_in[3];
    const float* Wg    = (const float*)d_in[4];
    const float* Wd    = (const float*)d_in[5];
    const float* pb    = (const float*)d_in[6];
    const float* pwg   = (const float*)d_in[7];
    const float* pwd   = (const float*)d_in[8];
    float* out = (float*)d_out;

    cudaFuncSetAttribute(pair_kernel, cudaFuncAttributeMaxDynamicSharedMemorySize,
                         SMEM_PAIR_TOTAL);

    softmax_cols<<<384, 128>>>(Wz, Wg, Wd);
    gemm_small<<<dim3(NNODE / 64, 3), 256>>>(z, gamma, delta, out);
    prep_split<<<NNODE, 128>>>(pwg, pwd);
    pair_kernel<<<4096, 256, SMEM_PAIR_TOTAL>>>(out, pb);
}

// round 13
// speedup vs baseline: 1.3874x; 1.1710x over previous
#include <cuda_runtime.h>
#include <cuda_fp16.h>
#include <cstdint>
#include <math.h>

#define NNODE 8192
#define DIN   512
#define DLAT  128
#define NSLOT 16               // fp16 split slots per latent k
#define KSPL  (DLAT * NSLOT)   // 2048

static const int OUT_NN = NNODE * NNODE;           // 67108864
static const int OUT_NL = NNODE * DLAT;            // 1048576

// ---------------- scratch (device globals; no allocation allowed) ----------
__device__ float g_T[3][DIN][DLAT];                // softmaxed transforms
__device__ float g_zd[NNODE * DLAT];
__device__ float g_ig[NNODE * DLAT];               // 1/(gd+SMALL)
__device__ float g_id[NNODE * DLAT];               // 1/(dd+SMALL)
__device__ __half g_U[(size_t)NNODE * KSPL];       // split-U (32 MB)
__device__ __half g_V[(size_t)NNODE * KSPL];       // split-V (32 MB)

// ---------------- K1: column softmax of the three W matrices ---------------
__global__ void softmax_cols(const float* __restrict__ Wz,
                             const float* __restrict__ Wg,
                             const float* __restrict__ Wd) {
    int mat = blockIdx.x >> 7;        // 0..2
    int col = blockIdx.x & 127;
    const float* W = (mat == 0) ? Wz : (mat == 1) ? Wg : Wd;
    int t = threadIdx.x;              // 128 threads
    __shared__ float red[128];

    float v[4];
#pragma unroll
    for (int r = 0; r < 4; r++) v[r] = W[(t + r * 128) * DLAT + col];

    float m = fmaxf(fmaxf(v[0], v[1]), fmaxf(v[2], v[3]));
    red[t] = m; __syncthreads();
    for (int s = 64; s > 0; s >>= 1) {
        if (t < s) red[t] = fmaxf(red[t], red[t + s]);
        __syncthreads();
    }
    m = red[0]; __syncthreads();

    float e[4], sum = 0.f;
#pragma unroll
    for (int r = 0; r < 4; r++) { e[r] = expf(v[r] - m); sum += e[r]; }
    red[t] = sum; __syncthreads();
    for (int s = 64; s > 0; s >>= 1) {
        if (t < s) red[t] += red[t + s];
        __syncthreads();
    }
    float inv = 1.f / red[0];
#pragma unroll
    for (int r = 0; r < 4; r++) g_T[mat][t + r * 128][col] = e[r] * inv;
}

// ---------------- K2a: zd / gd / dd GEMMs (fp32 SIMT) ----------------------
__global__ __launch_bounds__(256) void gemm_small(const float* __restrict__ z,
                                                  const float* __restrict__ gamma,
                                                  const float* __restrict__ delta,
                                                  float* __restrict__ out) {
    __shared__ float As[32][65];      // [k][m] transposed
    __shared__ float Bs[32][128];

    int which = blockIdx.y;
    const float* A = (which == 0) ? z : (which == 1) ? gamma : delta;
    const float* B = &g_T[which][0][0];
    int r0 = blockIdx.x * 64;

    int tid = threadIdx.x;
    int ty = tid >> 4, tx = tid & 15;

    float acc[4][8];
#pragma unroll
    for (int i = 0; i < 4; i++)
#pragma unroll
        for (int j = 0; j < 8; j++) acc[i][j] = 0.f;

    for (int kc = 0; kc < DIN / 32; kc++) {
#pragma unroll
        for (int it = 0; it < 2; it++) {
            int linear = tid + it * 256;          // 0..511
            int arow = linear >> 3, ac4 = linear & 7;
            float4 va = *reinterpret_cast<const float4*>(
                &A[(r0 + arow) * DIN + kc * 32 + ac4 * 4]);
            As[ac4 * 4 + 0][arow] = va.x;
            As[ac4 * 4 + 1][arow] = va.y;
            As[ac4 * 4 + 2][arow] = va.z;
            As[ac4 * 4 + 3][arow] = va.w;
        }
#pragma unroll
        for (int it = 0; it < 4; it++) {
            int linear = tid + it * 256;          // 0..1023
            int brow = linear >> 5, bc4 = linear & 31;
            *reinterpret_cast<float4*>(&Bs[brow][bc4 * 4]) =
                *reinterpret_cast<const float4*>(&B[(kc * 32 + brow) * DLAT + bc4 * 4]);
        }
        __syncthreads();

#pragma unroll
        for (int kk = 0; kk < 32; kk++) {
            float a[4];
#pragma unroll
            for (int i = 0; i < 4; i++) a[i] = As[kk][ty * 4 + i];
            float4 b0 = *reinterpret_cast<float4*>(&Bs[kk][tx * 4]);
            float4 b1 = *reinterpret_cast<float4*>(&Bs[kk][64 + tx * 4]);
#pragma unroll
            for (int i = 0; i < 4; i++) {
                acc[i][0] = fmaf(a[i], b0.x, acc[i][0]);
                acc[i][1] = fmaf(a[i], b0.y, acc[i][1]);
                acc[i][2] = fmaf(a[i], b0.z, acc[i][2]);
                acc[i][3] = fmaf(a[i], b0.w, acc[i][3]);
                acc[i][4] = fmaf(a[i], b1.x, acc[i][4]);
                acc[i][5] = fmaf(a[i], b1.y, acc[i][5]);
                acc[i][6] = fmaf(a[i], b1.z, acc[i][6]);
                acc[i][7] = fmaf(a[i], b1.w, acc[i][7]);
            }
        }
        __syncthreads();
    }

#pragma unroll
    for (int i = 0; i < 4; i++) {
        int node = r0 + ty * 4 + i;
#pragma unroll
        for (int j = 0; j < 8; j++) {
            int col = (j < 4) ? (tx * 4 + j) : (64 + tx * 4 + (j - 4));
            int idx = node * DLAT + col;
            float v = acc[i][j];
            if (which == 0) {
                g_zd[idx] = v;
                out[OUT_NN + idx] = v;
            } else if (which == 1) {
                out[OUT_NN + OUT_NL + idx] = v;
                g_ig[idx] = 1.f / (v + 1e-16f);
            } else {
                out[OUT_NN + 2 * OUT_NL + idx] = v;
                g_id[idx] = 1.f / (v + 1e-16f);
            }
        }
    }
}

// ---------------- K2b: build telescoped fp16-split U, V ---------------------
__device__ __forceinline__ void split2(float x, float& h, float& l) {
    h = __half2float(__float2half_rn(x));
    l = x - h;
}

__global__ __launch_bounds__(128) void prep_split(const float* __restrict__ pwg,
                                                  const float* __restrict__ pwd) {
    int i = blockIdx.x;
    int k = threadIdx.x;          // 0..127
    float zd = g_zd[i * DLAT + k];
    float ig = g_ig[i * DLAT + k];
    float id = g_id[i * DLAT + k];
    float z2 = zd * zd;
    float wgn = (*pwg) * 8192.0f;
    float wdn = (*pwd) * 8192.0f;

    float u1 = -(wgn * ig * z2);      // pairs with v=1
    float v6 = wdn * z2 * id;         // pairs with u=-1
    float U2 = (2.f * wgn * ig * zd) * 0.03125f;
    float V2 = zd * 32.f;
    float U3 = -(wgn * ig) * 0.0078125f;
    float V3 = z2 * 128.f;
    float U4 = -z2 * 128.f;
    float V4 = (wdn * id) * 0.0078125f;
    float U5 = (2.f * zd) * 16.f;
    float V5 = (wdn * zd * id) * 0.0625f;

    const float S  = 256.f;
    const float SI = 0.00390625f;

    float us[NSLOT], vs[NSLOT];
    float h, l;

    split2(u1, h, l);
    us[0] = h;       vs[0] = 1.f;
    us[1] = l * S;   vs[1] = SI;

#define PG(b, U, V) { float uh, ul, vh, vl; split2(U, uh, ul); split2(V, vh, vl); \
    us[(b)+0] = uh;      vs[(b)+0] = vh;       \
    us[(b)+1] = uh * SI; vs[(b)+1] = vl * S;   \
    us[(b)+2] = ul * S;  vs[(b)+2] = vh * SI; }

    PG(2,  U2, V2)
    PG(5,  U3, V3)
    PG(8,  U4, V4)
    PG(11, U5, V5)
#undef PG

    split2(v6, h, l);
    us[14] = -1.f;  vs[14] = h;
    us[15] = -SI;   vs[15] = l * S;

    __half hu[NSLOT], hv[NSLOT];
#pragma unroll
    for (int s = 0; s < NSLOT; s++) {
        hu[s] = __float2half_rn(us[s]);
        hv[s] = __float2half_rn(vs[s]);
    }
    size_t base = (size_t)i * KSPL + (size_t)k * NSLOT;
    *reinterpret_cast<uint4*>(&g_U[base])     = *reinterpret_cast<uint4*>(&hu[0]);
    *reinterpret_cast<uint4*>(&g_U[base + 8]) = *reinterpret_cast<uint4*>(&hu[8]);
    *reinterpret_cast<uint4*>(&g_V[base])     = *reinterpret_cast<uint4*>(&hv[0]);
    *reinterpret_cast<uint4*>(&g_V[base + 8]) = *reinterpret_cast<uint4*>(&hv[8]);
}

// ---------------- K3: 8192x8192x2048 fp16 mma.sync GEMM --------------------
// Block tile 128x128, warp grid 2x4, warp tile 64x32 (4x4 m16n8 frags).
// 2 CTAs/SM, KC=64 chunks, 3-stage cp.async ring, ONE sync per 64-K chunk.
__device__ __forceinline__ uint32_t smem_u32(const void* p) {
    uint32_t a;
    asm("{ .reg .u64 t; cvta.to.shared.u64 t, %1; cvt.u32.u64 %0, t; }"
        : "=r"(a) : "l"(p));
    return a;
}
__device__ __forceinline__ void ldsm_x4(uint32_t& r0, uint32_t& r1,
                                        uint32_t& r2, uint32_t& r3, uint32_t addr) {
    asm volatile("ldmatrix.sync.aligned.m8n8.x4.shared.b16 {%0,%1,%2,%3}, [%4];\n"
                 : "=r"(r0), "=r"(r1), "=r"(r2), "=r"(r3) : "r"(addr));
}
__device__ __forceinline__ void mma_fp16(float& c0, float& c1, float& c2, float& c3,
                                         uint32_t a0, uint32_t a1, uint32_t a2, uint32_t a3,
                                         uint32_t b0, uint32_t b1) {
    asm volatile("mma.sync.aligned.m16n8k16.row.col.f32.f16.f16.f32 "
                 "{%0,%1,%2,%3}, {%4,%5,%6,%7}, {%8,%9}, {%0,%1,%2,%3};\n"
                 : "+f"(c0), "+f"(c1), "+f"(c2), "+f"(c3)
                 : "r"(a0), "r"(a1), "r"(a2), "r"(a3), "r"(b0), "r"(b1));
}
#define CP_ASYNC16(sm, gm) \
    asm volatile("cp.async.cg.shared.global [%0], [%1], 16;\n" :: "r"(sm), "l"(gm))
#define CP_COMMIT() asm volatile("cp.async.commit_group;\n" ::: "memory")
#define CP_WAIT(n)  asm volatile("cp.async.wait_group %0;\n" :: "n"(n) : "memory")

__device__ __forceinline__ float fast_sigmoid(float x) {
    if (x < -88.f) return 0.f;
    return 1.f / (1.f + expf(-x));
}

#define SPAD   72                 // halves per smem row (144 B; conflict-free ldsm)
#define TM     128
#define TN     128
#define KC     64
#define NCHUNK (KSPL / KC)        // 32
#define STAGES 3
#define SA_BYTES (TM * SPAD * 2)  // 18432
#define SB_BYTES (TN * SPAD * 2)  // 18432
#define STAGE_BYTES (SA_BYTES + SB_BYTES)               // 36864
#define SMEM_PAIR_TOTAL (STAGES * STAGE_BYTES)          // 110592

__global__ __launch_bounds__(256, 2) void pair_kernel(float* __restrict__ out,
                                                      const float* __restrict__ pb) {
    extern __shared__ __align__(128) char smem[];
    uint32_t sbase = smem_u32(smem);

    int tid = threadIdx.x;
    int lane = tid & 31, wid = tid >> 5;
    int warpM = wid >> 2, warpN = wid & 3;   // 2 x 4 warps; warp tile 64x32

    // tile swizzle: groups of 16 brows x 64 bcols keep wave working set in L2
    int bx = blockIdx.x;                     // 0..4095 (64 brows x 64 bcols)
    int brow = ((bx >> 10) << 4) + ((bx & 1023) >> 6);
    int bcol = bx & 63;
    int i0 = brow * TM, j0 = bcol * TN;

    float acc[4][4][4];
#pragma unroll
    for (int a = 0; a < 4; a++)
#pragma unroll
        for (int b = 0; b < 4; b++)
#pragma unroll
            for (int c = 0; c < 4; c++) acc[a][b][c] = 0.f;

    // cp.async lane mapping: 128 rows x 8 quads(16B); 256 threads -> 4 iters
    int arow[4], aqi[4];
#pragma unroll
    for (int it = 0; it < 4; it++) { int q = tid + it * 256; arow[it] = q >> 3; aqi[it] = q & 7; }

#define ISSUE_CHUNK(c, s) {                                                       \
    uint32_t sa = sbase + (s) * STAGE_BYTES;                                      \
    uint32_t sb = sa + SA_BYTES;                                                  \
    _Pragma("unroll")                                                             \
    for (int it = 0; it < 4; it++)                                                \
        CP_ASYNC16(sa + (uint32_t)(arow[it] * 144 + aqi[it] * 16),                \
                   &g_U[(size_t)(i0 + arow[it]) * KSPL + (c) * KC + aqi[it] * 8]);\
    _Pragma("unroll")                                                             \
    for (int it = 0; it < 4; it++)                                                \
        CP_ASYNC16(sb + (uint32_t)(arow[it] * 144 + aqi[it] * 16),                \
                   &g_V[(size_t)(j0 + arow[it]) * KSPL + (c) * KC + aqi[it] * 8]);\
    CP_COMMIT(); }

    // ldmatrix lane offsets (x4 layout for both A and B)
    int a_m = (lane & 7) + ((lane >> 3) & 1) * 8;   // + warpM*64 + mf*16
    int a_k = ((lane >> 4) & 1) * 8;                // + ks*16
    int b_n = (lane & 7) + ((lane >> 4) & 1) * 8;   // + warpN*32 + nfp*16
    int b_k = ((lane >> 3) & 1) * 8;                // + ks*16

    // prologue: fill STAGES-1 stages
    ISSUE_CHUNK(0, 0);
    ISSUE_CHUNK(1, 1);

#pragma unroll 1
    for (int c = 0; c < NCHUNK; c++) {
        int st = c % STAGES;
        CP_WAIT(1);                   // own groups for chunk c complete
        __syncthreads();              // all threads' chunk-c data visible; stage
                                      // (c+2)%STAGES free (last read at c-1)
        if (c + 2 < NCHUNK) { ISSUE_CHUNK(c + 2, (c + 2) % STAGES); }
        else                { CP_COMMIT(); }   // keep group-count invariant

        uint32_t baseA = sbase + st * STAGE_BYTES;
        uint32_t baseB = baseA + SA_BYTES;
#pragma unroll
        for (int ks = 0; ks < 4; ks++) {
            uint32_t af[4][4], bf[2][4];
#pragma unroll
            for (int mf = 0; mf < 4; mf++) {
                int mm = warpM * 64 + mf * 16 + a_m;
                int kk = ks * 16 + a_k;
                ldsm_x4(af[mf][0], af[mf][1], af[mf][2], af[mf][3],
                        baseA + (uint32_t)(mm * SPAD + kk) * 2u);
            }
#pragma unroll
            for (int nfp = 0; nfp < 2; nfp++) {
                int nn = warpN * 32 + nfp * 16 + b_n;
                int kk = ks * 16 + b_k;
                ldsm_x4(bf[nfp][0], bf[nfp][1], bf[nfp][2], bf[nfp][3],
                        baseB + (uint32_t)(nn * SPAD + kk) * 2u);
            }
#pragma unroll
            for (int mf = 0; mf < 4; mf++)
#pragma unroll
                for (int nfp = 0; nfp < 2; nfp++) {
                    mma_fp16(acc[mf][2*nfp][0], acc[mf][2*nfp][1],
                             acc[mf][2*nfp][2], acc[mf][2*nfp][3],
                             af[mf][0], af[mf][1], af[mf][2], af[mf][3],
                             bf[nfp][0], bf[nfp][1]);
                    mma_fp16(acc[mf][2*nfp+1][0], acc[mf][2*nfp+1][1],
                             acc[mf][2*nfp+1][2], acc[mf][2*nfp+1][3],
                             af[mf][0], af[mf][1], af[mf][2], af[mf][3],
                             bf[nfp][2], bf[nfp][3]);
                }
        }
    }

    // epilogue: x = acc + bias ; sigmoid with exact-underflow fast path
    float bias = *pb;
    int lr = lane >> 2, lc = (lane & 3) * 2;
#pragma unroll
    for (int mf = 0; mf < 4; mf++) {
#pragma unroll
        for (int nf = 0; nf < 4; nf++) {
            int i1 = i0 + warpM * 64 + mf * 16 + lr;
            int j = j0 + warpN * 32 + (nf >> 1) * 16 + (nf & 1) * 8 + lc;
#pragma unroll
            for (int half = 0; half < 2; half++) {
                int i = i1 + half * 8;
                float x0 = acc[mf][nf][half * 2 + 0] + bias;
                float x1 = acc[mf][nf][half * 2 + 1] + bias;
                float2 r;
                r.x = fast_sigmoid(x0);
                r.y = fast_sigmoid(x1);
                *reinterpret_cast<float2*>(&out[(size_t)i * NNODE + j]) = r;
            }
        }
    }
}

// ---------------- launch -----------------------------------------------------
extern "C" void kernel_launch(void* const* d_in, const int* in_sizes, int n_in,
                              void* d_out, int out_size) {
    const float* z     = (const float*)d_in[0];
    const float* gamma = (const float*)d_in[1];
    const float* delta = (const float*)d_in[2];
    const float* Wz    = (const float*)d_in[3];
    const float* Wg    = (const float*)d_in[4];
    const float* Wd    = (const float*)d_in[5];
    const float* pb    = (const float*)d_in[6];
    const float* pwg   = (const float*)d_in[7];
    const float* pwd   = (const float*)d_in[8];
    float* out = (float*)d_out;

    cudaFuncSetAttribute(pair_kernel, cudaFuncAttributeMaxDynamicSharedMemorySize,
                         SMEM_PAIR_TOTAL);

    softmax_cols<<<384, 128>>>(Wz, Wg, Wd);
    gemm_small<<<dim3(NNODE / 64, 3), 256>>>(z, gamma, delta, out);
    prep_split<<<NNODE, 128>>>(pwg, pwd);
    pair_kernel<<<4096, 256, SMEM_PAIR_TOTAL>>>(out, pb);
}

// round 14
// speedup vs baseline: 1.4420x; 1.0393x over previous
#include <cuda_runtime.h>
#include <cuda_fp16.h>
#include <cstdint>
#include <math.h>

#define NNODE 8192
#define DIN   512
#define DLAT  128
#define NSLOT 16               // fp16 split slots per latent k
#define KSPL  (DLAT * NSLOT)   // 2048

static const int OUT_NN = NNODE * NNODE;           // 67108864
static const int OUT_NL = NNODE * DLAT;            // 1048576

// ---------------- scratch (device globals; no allocation allowed) ----------
__device__ float g_T[3][DIN][DLAT];                // softmaxed transforms
__device__ float g_zd[NNODE * DLAT];
__device__ float g_ig[NNODE * DLAT];               // 1/(gd+SMALL)
__device__ float g_id[NNODE * DLAT];               // 1/(dd+SMALL)
__device__ __half g_U[(size_t)NNODE * KSPL];       // split-U (32 MB)
__device__ __half g_V[(size_t)NNODE * KSPL];       // split-V (32 MB)

// ---------------- shared PTX helpers ----------------------------------------
__device__ __forceinline__ uint32_t smem_u32(const void* p) {
    uint32_t a;
    asm("{ .reg .u64 t; cvta.to.shared.u64 t, %1; cvt.u32.u64 %0, t; }"
        : "=r"(a) : "l"(p));
    return a;
}
__device__ __forceinline__ void ldsm_x4(uint32_t& r0, uint32_t& r1,
                                        uint32_t& r2, uint32_t& r3, uint32_t addr) {
    asm volatile("ldmatrix.sync.aligned.m8n8.x4.shared.b16 {%0,%1,%2,%3}, [%4];\n"
                 : "=r"(r0), "=r"(r1), "=r"(r2), "=r"(r3) : "r"(addr));
}
__device__ __forceinline__ void mma_fp16(float& c0, float& c1, float& c2, float& c3,
                                         uint32_t a0, uint32_t a1, uint32_t a2, uint32_t a3,
                                         uint32_t b0, uint32_t b1) {
    asm volatile("mma.sync.aligned.m16n8k16.row.col.f32.f16.f16.f32 "
                 "{%0,%1,%2,%3}, {%4,%5,%6,%7}, {%8,%9}, {%0,%1,%2,%3};\n"
                 : "+f"(c0), "+f"(c1), "+f"(c2), "+f"(c3)
                 : "r"(a0), "r"(a1), "r"(a2), "r"(a3), "r"(b0), "r"(b1));
}
#define CP_ASYNC16(sm, gm) \
    asm volatile("cp.async.cg.shared.global [%0], [%1], 16;\n" :: "r"(sm), "l"(gm))
#define CP_COMMIT() asm volatile("cp.async.commit_group;\n" ::: "memory")
#define CP_WAIT(n)  asm volatile("cp.async.wait_group %0;\n" :: "n"(n) : "memory")

// ---------------- K1: column softmax of the three W matrices ---------------
__global__ void softmax_cols(const float* __restrict__ Wz,
                             const float* __restrict__ Wg,
                             const float* __restrict__ Wd) {
    int mat = blockIdx.x >> 7;        // 0..2
    int col = blockIdx.x & 127;
    const float* W = (mat == 0) ? Wz : (mat == 1) ? Wg : Wd;
    int t = threadIdx.x;              // 128 threads
    __shared__ float red[128];

    float v[4];
#pragma unroll
    for (int r = 0; r < 4; r++) v[r] = W[(t + r * 128) * DLAT + col];

    float m = fmaxf(fmaxf(v[0], v[1]), fmaxf(v[2], v[3]));
    red[t] = m; __syncthreads();
    for (int s = 64; s > 0; s >>= 1) {
        if (t < s) red[t] = fmaxf(red[t], red[t + s]);
        __syncthreads();
    }
    m = red[0]; __syncthreads();

    float e[4], sum = 0.f;
#pragma unroll
    for (int r = 0; r < 4; r++) { e[r] = expf(v[r] - m); sum += e[r]; }
    red[t] = sum; __syncthreads();
    for (int s = 64; s > 0; s >>= 1) {
        if (t < s) red[t] += red[t + s];
        __syncthreads();
    }
    float inv = 1.f / red[0];
#pragma unroll
    for (int r = 0; r < 4; r++) g_T[mat][t + r * 128][col] = e[r] * inv;
}

// ---------------- K2a: zd / gd / dd GEMMs (fp16-split tensor cores) --------
// D = A(8192x512) @ T(512x128) per matrix, computed as K=1536 fp16 GEMM:
// per fp32-k, 3 slot-planes: (Ah,Bh), (Ah*2^-10, Bl*2^10), (Al*4, Bh/4).
// Residual ~2^-22 relative. Block tile 128x128, warp 64x32, chunk 32 fp32 k.
#define GSP   104                 // halves per smem row (208 B, 16B-multiple)
#define GS_BYTES (128 * GSP * 2)  // 26624 per operand
#define GS_TOTAL (2 * GS_BYTES)   // 53248

__global__ __launch_bounds__(256) void gemm_small_tc(const float* __restrict__ z,
                                                     const float* __restrict__ gamma,
                                                     const float* __restrict__ delta,
                                                     float* __restrict__ out) {
    extern __shared__ __align__(128) char gsm[];
    __half* sA = reinterpret_cast<__half*>(gsm);
    __half* sB = reinterpret_cast<__half*>(gsm + GS_BYTES);
    uint32_t sbA = smem_u32(sA), sbB = smem_u32(sB);

    int which = blockIdx.y;
    const float* A = (which == 0) ? z : (which == 1) ? gamma : delta;
    const float* B = &g_T[which][0][0];
    int r0 = blockIdx.x * 128;

    int tid = threadIdx.x;
    int lane = tid & 31, wid = tid >> 5;
    int warpM = wid >> 2, warpN = wid & 3;   // 2 x 4 warps; warp tile 64x32

    float acc[4][4][4];
#pragma unroll
    for (int a = 0; a < 4; a++)
#pragma unroll
        for (int b = 0; b < 4; b++)
#pragma unroll
            for (int c = 0; c < 4; c++) acc[a][b][c] = 0.f;

    int row = tid >> 1;        // 0..127 (A row / B col)
    int halfk = tid & 1;       // k-offset 16*halfk

    // ldmatrix lane offsets (identical to pair_kernel)
    int a_m = (lane & 7) + ((lane >> 3) & 1) * 8;
    int a_k = ((lane >> 4) & 1) * 8;
    int b_n = (lane & 7) + ((lane >> 4) & 1) * 8;
    int b_k = ((lane >> 3) & 1) * 8;

    const float S10 = 0.0009765625f;  // 2^-10
    const float S10I = 1024.f;

    for (int kc = 0; kc < DIN / 32; kc++) {
        // ---- load + convert A: 128 x 32 fp32 -> 3 slot-planes of 32 halves
        {
            const float4* ap = reinterpret_cast<const float4*>(
                &A[(size_t)(r0 + row) * DIN + kc * 32 + halfk * 16]);
            float4 w0 = ap[0], w1 = ap[1], w2 = ap[2], w3 = ap[3];
            float av[16] = {w0.x, w0.y, w0.z, w0.w, w1.x, w1.y, w1.z, w1.w,
                            w2.x, w2.y, w2.z, w2.w, w3.x, w3.y, w3.z, w3.w};
            __half p0[16], p1[16], p2[16];
#pragma unroll
            for (int i = 0; i < 16; i++) {
                float a = av[i];
                __half ah = __float2half_rn(a);
                float ahf = __half2float(ah);
                float al = a - ahf;
                p0[i] = ah;
                p1[i] = __float2half_rn(ahf * S10);
                p2[i] = __float2half_rn(al * 4.f);
            }
            __half* dst = &sA[row * GSP];
            *reinterpret_cast<uint4*>(&dst[0 * 32 + halfk * 16])     = *reinterpret_cast<uint4*>(&p0[0]);
            *reinterpret_cast<uint4*>(&dst[0 * 32 + halfk * 16 + 8]) = *reinterpret_cast<uint4*>(&p0[8]);
            *reinterpret_cast<uint4*>(&dst[1 * 32 + halfk * 16])     = *reinterpret_cast<uint4*>(&p1[0]);
            *reinterpret_cast<uint4*>(&dst[1 * 32 + halfk * 16 + 8]) = *reinterpret_cast<uint4*>(&p1[8]);
            *reinterpret_cast<uint4*>(&dst[2 * 32 + halfk * 16])     = *reinterpret_cast<uint4*>(&p2[0]);
            *reinterpret_cast<uint4*>(&dst[2 * 32 + halfk * 16 + 8]) = *reinterpret_cast<uint4*>(&p2[8]);
        }
        // ---- load + convert B (transpose): g_T[k][n] -> sB[n][slots]
        {
            float bv[16];
#pragma unroll
            for (int i = 0; i < 16; i++)
                bv[i] = B[(size_t)(kc * 32 + halfk * 16 + i) * DLAT + row];
            __half q0[16], q1[16], q2[16];
#pragma unroll
            for (int i = 0; i < 16; i++) {
                float b = bv[i];
                __half bh = __float2half_rn(b);
                float bhf = __half2float(bh);
                float bl = b - bhf;
                q0[i] = bh;
                q1[i] = __float2half_rn(bl * S10I);
                q2[i] = __float2half_rn(bhf * 0.25f);
            }
            __half* dst = &sB[row * GSP];
            *reinterpret_cast<uint4*>(&dst[0 * 32 + halfk * 16])     = *reinterpret_cast<uint4*>(&q0[0]);
            *reinterpret_cast<uint4*>(&dst[0 * 32 + halfk * 16 + 8]) = *reinterpret_cast<uint4*>(&q0[8]);
            *reinterpret_cast<uint4*>(&dst[1 * 32 + halfk * 16])     = *reinterpret_cast<uint4*>(&q1[0]);
            *reinterpret_cast<uint4*>(&dst[1 * 32 + halfk * 16 + 8]) = *reinterpret_cast<uint4*>(&q1[8]);
            *reinterpret_cast<uint4*>(&dst[2 * 32 + halfk * 16])     = *reinterpret_cast<uint4*>(&q2[0]);
            *reinterpret_cast<uint4*>(&dst[2 * 32 + halfk * 16 + 8]) = *reinterpret_cast<uint4*>(&q2[8]);
        }
        __syncthreads();

        // ---- 96 slots = 6 x k16 mma steps
#pragma unroll
        for (int ks = 0; ks < 6; ks++) {
            uint32_t af[4][4], bf[2][4];
#pragma unroll
            for (int mf = 0; mf < 4; mf++) {
                int mm = warpM * 64 + mf * 16 + a_m;
                int kk = ks * 16 + a_k;
                ldsm_x4(af[mf][0], af[mf][1], af[mf][2], af[mf][3],
                        sbA + (uint32_t)(mm * GSP + kk) * 2u);
            }
#pragma unroll
            for (int nfp = 0; nfp < 2; nfp++) {
                int nn = warpN * 32 + nfp * 16 + b_n;
                int kk = ks * 16 + b_k;
                ldsm_x4(bf[nfp][0], bf[nfp][1], bf[nfp][2], bf[nfp][3],
                        sbB + (uint32_t)(nn * GSP + kk) * 2u);
            }
#pragma unroll
            for (int mf = 0; mf < 4; mf++)
#pragma unroll
                for (int nfp = 0; nfp < 2; nfp++) {
                    mma_fp16(acc[mf][2*nfp][0], acc[mf][2*nfp][1],
                             acc[mf][2*nfp][2], acc[mf][2*nfp][3],
                             af[mf][0], af[mf][1], af[mf][2], af[mf][3],
                             bf[nfp][0], bf[nfp][1]);
                    mma_fp16(acc[mf][2*nfp+1][0], acc[mf][2*nfp+1][1],
                             acc[mf][2*nfp+1][2], acc[mf][2*nfp+1][3],
                             af[mf][0], af[mf][1], af[mf][2], af[mf][3],
                             bf[nfp][2], bf[nfp][3]);
                }
        }
        __syncthreads();
    }

    // ---- epilogue: scatter to g_zd/g_ig/g_id and the out tail sections
    int lr = lane >> 2, lc = (lane & 3) * 2;
#pragma unroll
    for (int mf = 0; mf < 4; mf++) {
#pragma unroll
        for (int nf = 0; nf < 4; nf++) {
            int col = warpN * 32 + (nf >> 1) * 16 + (nf & 1) * 8 + lc;
#pragma unroll
            for (int half = 0; half < 2; half++) {
                int node = r0 + warpM * 64 + mf * 16 + lr + half * 8;
                float v0 = acc[mf][nf][half * 2 + 0];
                float v1 = acc[mf][nf][half * 2 + 1];
                int idx = node * DLAT + col;
                if (which == 0) {
                    g_zd[idx] = v0;  g_zd[idx + 1] = v1;
                    out[OUT_NN + idx] = v0;  out[OUT_NN + idx + 1] = v1;
                } else if (which == 1) {
                    out[OUT_NN + OUT_NL + idx] = v0;
                    out[OUT_NN + OUT_NL + idx + 1] = v1;
                    g_ig[idx]     = 1.f / (v0 + 1e-16f);
                    g_ig[idx + 1] = 1.f / (v1 + 1e-16f);
                } else {
                    out[OUT_NN + 2 * OUT_NL + idx] = v0;
                    out[OUT_NN + 2 * OUT_NL + idx + 1] = v1;
                    g_id[idx]     = 1.f / (v0 + 1e-16f);
                    g_id[idx + 1] = 1.f / (v1 + 1e-16f);
                }
            }
        }
    }
}

// ---------------- K2b: build telescoped fp16-split U, V ---------------------
__device__ __forceinline__ void split2(float x, float& h, float& l) {
    h = __half2float(__float2half_rn(x));
    l = x - h;
}

__global__ __launch_bounds__(128) void prep_split(const float* __restrict__ pwg,
                                                  const float* __restrict__ pwd) {
    int i = blockIdx.x;
    int k = threadIdx.x;          // 0..127
    float zd = g_zd[i * DLAT + k];
    float ig = g_ig[i * DLAT + k];
    float id = g_id[i * DLAT + k];
    float z2 = zd * zd;
    float wgn = (*pwg) * 8192.0f;
    float wdn = (*pwd) * 8192.0f;

    float u1 = -(wgn * ig * z2);      // pairs with v=1
    float v6 = wdn * z2 * id;         // pairs with u=-1
    float U2 = (2.f * wgn * ig * zd) * 0.03125f;
    float V2 = zd * 32.f;
    float U3 = -(wgn * ig) * 0.0078125f;
    float V3 = z2 * 128.f;
    float U4 = -z2 * 128.f;
    float V4 = (wdn * id) * 0.0078125f;
    float U5 = (2.f * zd) * 16.f;
    float V5 = (wdn * zd * id) * 0.0625f;

    const float S  = 256.f;
    const float SI = 0.00390625f;

    float us[NSLOT], vs[NSLOT];
    float h, l;

    split2(u1, h, l);
    us[0] = h;       vs[0] = 1.f;
    us[1] = l * S;   vs[1] = SI;

#define PG(b, U, V) { float uh, ul, vh, vl; split2(U, uh, ul); split2(V, vh, vl); \
    us[(b)+0] = uh;      vs[(b)+0] = vh;       \
    us[(b)+1] = uh * SI; vs[(b)+1] = vl * S;   \
    us[(b)+2] = ul * S;  vs[(b)+2] = vh * SI; }

    PG(2,  U2, V2)
    PG(5,  U3, V3)
    PG(8,  U4, V4)
    PG(11, U5, V5)
#undef PG

    split2(v6, h, l);
    us[14] = -1.f;  vs[14] = h;
    us[15] = -SI;   vs[15] = l * S;

    __half hu[NSLOT], hv[NSLOT];
#pragma unroll
    for (int s = 0; s < NSLOT; s++) {
        hu[s] = __float2half_rn(us[s]);
        hv[s] = __float2half_rn(vs[s]);
    }
    size_t base = (size_t)i * KSPL + (size_t)k * NSLOT;
    *reinterpret_cast<uint4*>(&g_U[base])     = *reinterpret_cast<uint4*>(&hu[0]);
    *reinterpret_cast<uint4*>(&g_U[base + 8]) = *reinterpret_cast<uint4*>(&hu[8]);
    *reinterpret_cast<uint4*>(&g_V[base])     = *reinterpret_cast<uint4*>(&hv[0]);
    *reinterpret_cast<uint4*>(&g_V[base + 8]) = *reinterpret_cast<uint4*>(&hv[8]);
}

// ---------------- K3: 8192x8192x2048 fp16 mma.sync GEMM --------------------
// Block tile 128x128, warp grid 2x4, warp tile 64x32 (4x4 m16n8 frags).
// 2 CTAs/SM, KC=64 chunks, 3-stage cp.async ring, ONE sync per 64-K chunk.
__device__ __forceinline__ float fast_sigmoid(float x) {
    if (x < -88.f) return 0.f;
    return 1.f / (1.f + expf(-x));
}

#define SPAD   72                 // halves per smem row (144 B; conflict-free ldsm)
#define TM     128
#define TN     128
#define KC     64
#define NCHUNK (KSPL / KC)        // 32
#define STAGES 3
#define SA_BYTES (TM * SPAD * 2)  // 18432
#define SB_BYTES (TN * SPAD * 2)  // 18432
#define STAGE_BYTES (SA_BYTES + SB_BYTES)               // 36864
#define SMEM_PAIR_TOTAL (STAGES * STAGE_BYTES)          // 110592

__global__ __launch_bounds__(256, 2) void pair_kernel(float* __restrict__ out,
                                                      const float* __restrict__ pb) {
    extern __shared__ __align__(128) char smem[];
    uint32_t sbase = smem_u32(smem);

    int tid = threadIdx.x;
    int lane = tid & 31, wid = tid >> 5;
    int warpM = wid >> 2, warpN = wid & 3;   // 2 x 4 warps; warp tile 64x32

    // tile swizzle: groups of 16 brows x 64 bcols keep wave working set in L2
    int bx = blockIdx.x;                     // 0..4095 (64 brows x 64 bcols)
    int brow = ((bx >> 10) << 4) + ((bx & 1023) >> 6);
    int bcol = bx & 63;
    int i0 = brow * TM, j0 = bcol * TN;

    float acc[4][4][4];
#pragma unroll
    for (int a = 0; a < 4; a++)
#pragma unroll
        for (int b = 0; b < 4; b++)
#pragma unroll
            for (int c = 0; c < 4; c++) acc[a][b][c] = 0.f;

    // cp.async lane mapping: 128 rows x 8 quads(16B); 256 threads -> 4 iters
    int arow[4], aqi[4];
#pragma unroll
    for (int it = 0; it < 4; it++) { int q = tid + it * 256; arow[it] = q >> 3; aqi[it] = q & 7; }

#define ISSUE_CHUNK(c, s) {                                                       \
    uint32_t sa = sbase + (s) * STAGE_BYTES;                                      \
    uint32_t sb = sa + SA_BYTES;                                                  \
    _Pragma("unroll")                                                             \
    for (int it = 0; it < 4; it++)                                                \
        CP_ASYNC16(sa + (uint32_t)(arow[it] * 144 + aqi[it] * 16),                \
                   &g_U[(size_t)(i0 + arow[it]) * KSPL + (c) * KC + aqi[it] * 8]);\
    _Pragma("unroll")                                                             \
    for (int it = 0; it < 4; it++)                                                \
        CP_ASYNC16(sb + (uint32_t)(arow[it] * 144 + aqi[it] * 16),                \
                   &g_V[(size_t)(j0 + arow[it]) * KSPL + (c) * KC + aqi[it] * 8]);\
    CP_COMMIT(); }

    // ldmatrix lane offsets (x4 layout for both A and B)
    int a_m = (lane & 7) + ((lane >> 3) & 1) * 8;   // + warpM*64 + mf*16
    int a_k = ((lane >> 4) & 1) * 8;                // + ks*16
    int b_n = (lane & 7) + ((lane >> 4) & 1) * 8;   // + warpN*32 + nfp*16
    int b_k = ((lane >> 3) & 1) * 8;                // + ks*16

    // prologue: fill STAGES-1 stages
    ISSUE_CHUNK(0, 0);
    ISSUE_CHUNK(1, 1);

#pragma unroll 1
    for (int c = 0; c < NCHUNK; c++) {
        int st = c % STAGES;
        CP_WAIT(1);                   // own groups for chunk c complete
        __syncthreads();              // all threads' chunk-c data visible; stage
                                      // (c+2)%STAGES free (last read at c-1)
        if (c + 2 < NCHUNK) { ISSUE_CHUNK(c + 2, (c + 2) % STAGES); }
        else                { CP_COMMIT(); }   // keep group-count invariant

        uint32_t baseA = sbase + st * STAGE_BYTES;
        uint32_t baseB = baseA + SA_BYTES;
#pragma unroll
        for (int ks = 0; ks < 4; ks++) {
            uint32_t af[4][4], bf[2][4];
#pragma unroll
            for (int mf = 0; mf < 4; mf++) {
                int mm = warpM * 64 + mf * 16 + a_m;
                int kk = ks * 16 + a_k;
                ldsm_x4(af[mf][0], af[mf][1], af[mf][2], af[mf][3],
                        baseA + (uint32_t)(mm * SPAD + kk) * 2u);
            }
#pragma unroll
            for (int nfp = 0; nfp < 2; nfp++) {
                int nn = warpN * 32 + nfp * 16 + b_n;
                int kk = ks * 16 + b_k;
                ldsm_x4(bf[nfp][0], bf[nfp][1], bf[nfp][2], bf[nfp][3],
                        baseB + (uint32_t)(nn * SPAD + kk) * 2u);
            }
#pragma unroll
            for (int mf = 0; mf < 4; mf++)
#pragma unroll
                for (int nfp = 0; nfp < 2; nfp++) {
                    mma_fp16(acc[mf][2*nfp][0], acc[mf][2*nfp][1],
                             acc[mf][2*nfp][2], acc[mf][2*nfp][3],
                             af[mf][0], af[mf][1], af[mf][2], af[mf][3],
                             bf[nfp][0], bf[nfp][1]);
                    mma_fp16(acc[mf][2*nfp+1][0], acc[mf][2*nfp+1][1],
                             acc[mf][2*nfp+1][2], acc[mf][2*nfp+1][3],
                             af[mf][0], af[mf][1], af[mf][2], af[mf][3],
                             bf[nfp][2], bf[nfp][3]);
                }
        }
    }

    // epilogue: x = acc + bias ; sigmoid with exact-underflow fast path
    float bias = *pb;
    int lr = lane >> 2, lc = (lane & 3) * 2;
#pragma unroll
    for (int mf = 0; mf < 4; mf++) {
#pragma unroll
        for (int nf = 0; nf < 4; nf++) {
            int i1 = i0 + warpM * 64 + mf * 16 + lr;
            int j = j0 + warpN * 32 + (nf >> 1) * 16 + (nf & 1) * 8 + lc;
#pragma unroll
            for (int half = 0; half < 2; half++) {
                int i = i1 + half * 8;
                float x0 = acc[mf][nf][half * 2 + 0] + bias;
                float x1 = acc[mf][nf][half * 2 + 1] + bias;
                float2 r;
                r.x = fast_sigmoid(x0);
                r.y = fast_sigmoid(x1);
                *reinterpret_cast<float2*>(&out[(size_t)i * NNODE + j]) = r;
            }
        }
    }
}

// ---------------- launch -----------------------------------------------------
extern "C" void kernel_launch(void* const* d_in, const int* in_sizes, int n_in,
                              void* d_out, int out_size) {
    const float* z     = (const float*)d_in[0];
    const float* gamma = (const float*)d_in[1];
    const float* delta = (const float*)d_in[2];
    const float* Wz    = (const float*)d_in[3];
    const float* Wg    = (const float*)d_in[4];
    const float* Wd    = (const float*)d_in[5];
    const float* pb    = (const float*)d_in[6];
    const float* pwg   = (const float*)d_in[7];
    const float* pwd   = (const float*)d_in[8];
    float* out = (float*)d_out;

    cudaFuncSetAttribute(pair_kernel, cudaFuncAttributeMaxDynamicSharedMemorySize,
                         SMEM_PAIR_TOTAL);
    cudaFuncSetAttribute(gemm_small_tc, cudaFuncAttributeMaxDynamicSharedMemorySize,
                         GS_TOTAL);

    softmax_cols<<<384, 128>>>(Wz, Wg, Wd);
    gemm_small_tc<<<dim3(NNODE / 128, 3), 256, GS_TOTAL>>>(z, gamma, delta, out);
    prep_split<<<NNODE, 128>>>(pwg, pwd);
    pair_kernel<<<4096, 256, SMEM_PAIR_TOTAL>>>(out, pb);
}

// round 17
// speedup vs baseline: 1.6729x; 1.1601x over previous
#include <cuda_runtime.h>
#include <cuda_fp16.h>
#include <cstdint>
#include <math.h>

#define NNODE 8192
#define DIN   512
#define DLAT  128
#define NSLOT 16               // fp16 split slots per latent k
#define KSPL  (DLAT * NSLOT)   // 2048

static const int OUT_NN = NNODE * NNODE;           // 67108864
static const int OUT_NL = NNODE * DLAT;            // 1048576

// ---------------- scratch (device globals; no allocation allowed) ----------
__device__ float g_T[3][DIN][DLAT];                // softmaxed transforms
__device__ float g_zd[NNODE * DLAT];
__device__ float g_ig[NNODE * DLAT];               // 1/(gd+SMALL)
__device__ float g_id[NNODE * DLAT];               // 1/(dd+SMALL)
__device__ __half g_U[(size_t)NNODE * KSPL];       // split-U (32 MB)
__device__ __half g_V[(size_t)NNODE * KSPL];       // split-V (32 MB)

// ---------------- shared PTX helpers ----------------------------------------
__device__ __forceinline__ uint32_t smem_u32(const void* p) {
    uint32_t a;
    asm("{ .reg .u64 t; cvta.to.shared.u64 t, %1; cvt.u32.u64 %0, t; }"
        : "=r"(a) : "l"(p));
    return a;
}
__device__ __forceinline__ void ldsm_x4(uint32_t& r0, uint32_t& r1,
                                        uint32_t& r2, uint32_t& r3, uint32_t addr) {
    asm volatile("ldmatrix.sync.aligned.m8n8.x4.shared.b16 {%0,%1,%2,%3}, [%4];\n"
                 : "=r"(r0), "=r"(r1), "=r"(r2), "=r"(r3) : "r"(addr));
}
__device__ __forceinline__ void mma_fp16(float& c0, float& c1, float& c2, float& c3,
                                         uint32_t a0, uint32_t a1, uint32_t a2, uint32_t a3,
                                         uint32_t b0, uint32_t b1) {
    asm volatile("mma.sync.aligned.m16n8k16.row.col.f32.f16.f16.f32 "
                 "{%0,%1,%2,%3}, {%4,%5,%6,%7}, {%8,%9}, {%0,%1,%2,%3};\n"
                 : "+f"(c0), "+f"(c1), "+f"(c2), "+f"(c3)
                 : "r"(a0), "r"(a1), "r"(a2), "r"(a3), "r"(b0), "r"(b1));
}
#define CP_ASYNC16(sm, gm) \
    asm volatile("cp.async.cg.shared.global [%0], [%1], 16;\n" :: "r"(sm), "l"(gm))

#define MBARRIER_INIT(mbar, count) \
    asm volatile("mbarrier.init.shared.b64 [%0], %1;" \
                 :: "r"((uint32_t)(mbar)), "r"((uint32_t)(count)) : "memory")
#define MBARRIER_ARRIVE(mbar) \
    asm volatile("mbarrier.arrive.shared.b64 _, [%0];" \
                 :: "r"((uint32_t)(mbar)) : "memory")
// NOTE: .noinc is load-bearing — without it the pending count is incremented
// before the arrive (net zero) and a count-N barrier never completes.
#define CP_ASYNC_MBAR_ARRIVE(mbar) \
    asm volatile("cp.async.mbarrier.arrive.noinc.shared.b64 [%0];" \
                 :: "r"((uint32_t)(mbar)) : "memory")

#define MBARRIER_WAIT_PARITY(mbar, parity) do {                                   \
    uint32_t _mbar = (uint32_t)(mbar);                                            \
    uint32_t _par = (uint32_t)(parity);                                           \
    uint32_t _done;                                                               \
    asm volatile("{\n\t.reg .pred p;\n\t"                                         \
        "mbarrier.try_wait.parity.acquire.cta.shared::cta.b64 p, [%1], %2;\n\t"   \
        "selp.b32 %0, 1, 0, p;\n\t}"                                              \
        : "=r"(_done) : "r"(_mbar), "r"(_par) : "memory");                        \
    if (!_done) {                                                                 \
        asm volatile("{\n\t.reg .pred P1;\n\t"                                    \
            "WL_%=:\n\t"                                                          \
            "mbarrier.try_wait.parity.acquire.cta.shared::cta.b64 P1, [%0], %1, 0x989680;\n\t" \
            "@P1 bra.uni WD_%=;\n\t"                                              \
            "bra.uni WL_%=;\n\t"                                                  \
            "WD_%=:\n\t}"                                                         \
            :: "r"(_mbar), "r"(_par) : "memory");                                 \
    }                                                                             \
} while (0)

// ---------------- K1: column softmax of the three W matrices ---------------
__global__ void softmax_cols(const float* __restrict__ Wz,
                             const float* __restrict__ Wg,
                             const float* __restrict__ Wd) {
    int mat = blockIdx.x >> 7;        // 0..2
    int col = blockIdx.x & 127;
    const float* W = (mat == 0) ? Wz : (mat == 1) ? Wg : Wd;
    int t = threadIdx.x;              // 128 threads
    __shared__ float red[128];

    float v[4];
#pragma unroll
    for (int r = 0; r < 4; r++) v[r] = W[(t + r * 128) * DLAT + col];

    float m = fmaxf(fmaxf(v[0], v[1]), fmaxf(v[2], v[3]));
    red[t] = m; __syncthreads();
    for (int s = 64; s > 0; s >>= 1) {
        if (t < s) red[t] = fmaxf(red[t], red[t + s]);
        __syncthreads();
    }
    m = red[0]; __syncthreads();

    float e[4], sum = 0.f;
#pragma unroll
    for (int r = 0; r < 4; r++) { e[r] = expf(v[r] - m); sum += e[r]; }
    red[t] = sum; __syncthreads();
    for (int s = 64; s > 0; s >>= 1) {
        if (t < s) red[t] += red[t + s];
        __syncthreads();
    }
    float inv = 1.f / red[0];
#pragma unroll
    for (int r = 0; r < 4; r++) g_T[mat][t + r * 128][col] = e[r] * inv;
}

// ---------------- K2a: zd / gd / dd GEMMs (fp16-split tensor cores) --------
#define GSP   104                 // halves per smem row (208 B, 16B-multiple)
#define GS_BYTES (128 * GSP * 2)  // 26624 per operand
#define GS_TOTAL (2 * GS_BYTES)   // 53248

__global__ __launch_bounds__(256) void gemm_small_tc(const float* __restrict__ z,
                                                     const float* __restrict__ gamma,
                                                     const float* __restrict__ delta,
                                                     float* __restrict__ out) {
    extern __shared__ __align__(128) char gsm[];
    __half* sA = reinterpret_cast<__half*>(gsm);
    __half* sB = reinterpret_cast<__half*>(gsm + GS_BYTES);
    uint32_t sbA = smem_u32(sA), sbB = smem_u32(sB);

    int which = blockIdx.y;
    const float* A = (which == 0) ? z : (which == 1) ? gamma : delta;
    const float* B = &g_T[which][0][0];
    int r0 = blockIdx.x * 128;

    int tid = threadIdx.x;
    int lane = tid & 31, wid = tid >> 5;
    int warpM = wid >> 2, warpN = wid & 3;   // 2 x 4 warps; warp tile 64x32

    float acc[4][4][4];
#pragma unroll
    for (int a = 0; a < 4; a++)
#pragma unroll
        for (int b = 0; b < 4; b++)
#pragma unroll
            for (int c = 0; c < 4; c++) acc[a][b][c] = 0.f;

    int row = tid >> 1;        // 0..127 (A row / B col)
    int halfk = tid & 1;       // k-offset 16*halfk

    int a_m = (lane & 7) + ((lane >> 3) & 1) * 8;
    int a_k = ((lane >> 4) & 1) * 8;
    int b_n = (lane & 7) + ((lane >> 4) & 1) * 8;
    int b_k = ((lane >> 3) & 1) * 8;

    const float S10 = 0.0009765625f;  // 2^-10
    const float S10I = 1024.f;

    for (int kc = 0; kc < DIN / 32; kc++) {
        {
            const float4* ap = reinterpret_cast<const float4*>(
                &A[(size_t)(r0 + row) * DIN + kc * 32 + halfk * 16]);
            float4 w0 = ap[0], w1 = ap[1], w2 = ap[2], w3 = ap[3];
            float av[16] = {w0.x, w0.y, w0.z, w0.w, w1.x, w1.y, w1.z, w1.w,
                            w2.x, w2.y, w2.z, w2.w, w3.x, w3.y, w3.z, w3.w};
            __half p0[16], p1[16], p2[16];
#pragma unroll
            for (int i = 0; i < 16; i++) {
                float a = av[i];
                __half ah = __float2half_rn(a);
                float ahf = __half2float(ah);
                float al = a - ahf;
                p0[i] = ah;
                p1[i] = __float2half_rn(ahf * S10);
                p2[i] = __float2half_rn(al * 4.f);
            }
            __half* dst = &sA[row * GSP];
            *reinterpret_cast<uint4*>(&dst[0 * 32 + halfk * 16])     = *reinterpret_cast<uint4*>(&p0[0]);
            *reinterpret_cast<uint4*>(&dst[0 * 32 + halfk * 16 + 8]) = *reinterpret_cast<uint4*>(&p0[8]);
            *reinterpret_cast<uint4*>(&dst[1 * 32 + halfk * 16])     = *reinterpret_cast<uint4*>(&p1[0]);
            *reinterpret_cast<uint4*>(&dst[1 * 32 + halfk * 16 + 8]) = *reinterpret_cast<uint4*>(&p1[8]);
            *reinterpret_cast<uint4*>(&dst[2 * 32 + halfk * 16])     = *reinterpret_cast<uint4*>(&p2[0]);
            *reinterpret_cast<uint4*>(&dst[2 * 32 + halfk * 16 + 8]) = *reinterpret_cast<uint4*>(&p2[8]);
        }
        {
            float bv[16];
#pragma unroll
            for (int i = 0; i < 16; i++)
                bv[i] = B[(size_t)(kc * 32 + halfk * 16 + i) * DLAT + row];
            __half q0[16], q1[16], q2[16];
#pragma unroll
            for (int i = 0; i < 16; i++) {
                float b = bv[i];
                __half bh = __float2half_rn(b);
                float bhf = __half2float(bh);
                float bl = b - bhf;
                q0[i] = bh;
                q1[i] = __float2half_rn(bl * S10I);
                q2[i] = __float2half_rn(bhf * 0.25f);
            }
            __half* dst = &sB[row * GSP];
            *reinterpret_cast<uint4*>(&dst[0 * 32 + halfk * 16])     = *reinterpret_cast<uint4*>(&q0[0]);
            *reinterpret_cast<uint4*>(&dst[0 * 32 + halfk * 16 + 8]) = *reinterpret_cast<uint4*>(&q0[8]);
            *reinterpret_cast<uint4*>(&dst[1 * 32 + halfk * 16])     = *reinterpret_cast<uint4*>(&q1[0]);
            *reinterpret_cast<uint4*>(&dst[1 * 32 + halfk * 16 + 8]) = *reinterpret_cast<uint4*>(&q1[8]);
            *reinterpret_cast<uint4*>(&dst[2 * 32 + halfk * 16])     = *reinterpret_cast<uint4*>(&q2[0]);
            *reinterpret_cast<uint4*>(&dst[2 * 32 + halfk * 16 + 8]) = *reinterpret_cast<uint4*>(&q2[8]);
        }
        __syncthreads();

#pragma unroll
        for (int ks = 0; ks < 6; ks++) {
            uint32_t af[4][4], bf[2][4];
#pragma unroll
            for (int mf = 0; mf < 4; mf++) {
                int mm = warpM * 64 + mf * 16 + a_m;
                int kk = ks * 16 + a_k;
                ldsm_x4(af[mf][0], af[mf][1], af[mf][2], af[mf][3],
                        sbA + (uint32_t)(mm * GSP + kk) * 2u);
            }
#pragma unroll
            for (int nfp = 0; nfp < 2; nfp++) {
                int nn = warpN * 32 + nfp * 16 + b_n;
                int kk = ks * 16 + b_k;
                ldsm_x4(bf[nfp][0], bf[nfp][1], bf[nfp][2], bf[nfp][3],
                        sbB + (uint32_t)(nn * GSP + kk) * 2u);
            }
#pragma unroll
            for (int mf = 0; mf < 4; mf++)
#pragma unroll
                for (int nfp = 0; nfp < 2; nfp++) {
                    mma_fp16(acc[mf][2*nfp][0], acc[mf][2*nfp][1],
                             acc[mf][2*nfp][2], acc[mf][2*nfp][3],
                             af[mf][0], af[mf][1], af[mf][2], af[mf][3],
                             bf[nfp][0], bf[nfp][1]);
                    mma_fp16(acc[mf][2*nfp+1][0], acc[mf][2*nfp+1][1],
                             acc[mf][2*nfp+1][2], acc[mf][2*nfp+1][3],
                             af[mf][0], af[mf][1], af[mf][2], af[mf][3],
                             bf[nfp][2], bf[nfp][3]);
                }
        }
        __syncthreads();
    }

    int lr = lane >> 2, lc = (lane & 3) * 2;
#pragma unroll
    for (int mf = 0; mf < 4; mf++) {
#pragma unroll
        for (int nf = 0; nf < 4; nf++) {
            int col = warpN * 32 + (nf >> 1) * 16 + (nf & 1) * 8 + lc;
#pragma unroll
            for (int half = 0; half < 2; half++) {
                int node = r0 + warpM * 64 + mf * 16 + lr + half * 8;
                float v0 = acc[mf][nf][half * 2 + 0];
                float v1 = acc[mf][nf][half * 2 + 1];
                int idx = node * DLAT + col;
                if (which == 0) {
                    g_zd[idx] = v0;  g_zd[idx + 1] = v1;
                    out[OUT_NN + idx] = v0;  out[OUT_NN + idx + 1] = v1;
                } else if (which == 1) {
                    out[OUT_NN + OUT_NL + idx] = v0;
                    out[OUT_NN + OUT_NL + idx + 1] = v1;
                    g_ig[idx]     = 1.f / (v0 + 1e-16f);
                    g_ig[idx + 1] = 1.f / (v1 + 1e-16f);
                } else {
                    out[OUT_NN + 2 * OUT_NL + idx] = v0;
                    out[OUT_NN + 2 * OUT_NL + idx + 1] = v1;
                    g_id[idx]     = 1.f / (v0 + 1e-16f);
                    g_id[idx + 1] = 1.f / (v1 + 1e-16f);
                }
            }
        }
    }
}

// ---------------- K2b: build telescoped fp16-split U, V ---------------------
__device__ __forceinline__ void split2(float x, float& h, float& l) {
    h = __half2float(__float2half_rn(x));
    l = x - h;
}

__global__ __launch_bounds__(128) void prep_split(const float* __restrict__ pwg,
                                                  const float* __restrict__ pwd) {
    int i = blockIdx.x;
    int k = threadIdx.x;          // 0..127
    float zd = g_zd[i * DLAT + k];
    float ig = g_ig[i * DLAT + k];
    float id = g_id[i * DLAT + k];
    float z2 = zd * zd;
    float wgn = (*pwg) * 8192.0f;
    float wdn = (*pwd) * 8192.0f;

    float u1 = -(wgn * ig * z2);      // pairs with v=1
    float v6 = wdn * z2 * id;         // pairs with u=-1
    float U2 = (2.f * wgn * ig * zd) * 0.03125f;
    float V2 = zd * 32.f;
    float U3 = -(wgn * ig) * 0.0078125f;
    float V3 = z2 * 128.f;
    float U4 = -z2 * 128.f;
    float V4 = (wdn * id) * 0.0078125f;
    float U5 = (2.f * zd) * 16.f;
    float V5 = (wdn * zd * id) * 0.0625f;

    const float S  = 256.f;
    const float SI = 0.00390625f;

    float us[NSLOT], vs[NSLOT];
    float h, l;

    split2(u1, h, l);
    us[0] = h;       vs[0] = 1.f;
    us[1] = l * S;   vs[1] = SI;

#define PG(b, U, V) { float uh, ul, vh, vl; split2(U, uh, ul); split2(V, vh, vl); \
    us[(b)+0] = uh;      vs[(b)+0] = vh;       \
    us[(b)+1] = uh * SI; vs[(b)+1] = vl * S;   \
    us[(b)+2] = ul * S;  vs[(b)+2] = vh * SI; }

    PG(2,  U2, V2)
    PG(5,  U3, V3)
    PG(8,  U4, V4)
    PG(11, U5, V5)
#undef PG

    split2(v6, h, l);
    us[14] = -1.f;  vs[14] = h;
    us[15] = -SI;   vs[15] = l * S;

    __half hu[NSLOT], hv[NSLOT];
#pragma unroll
    for (int s = 0; s < NSLOT; s++) {
        hu[s] = __float2half_rn(us[s]);
        hv[s] = __float2half_rn(vs[s]);
    }
    size_t base = (size_t)i * KSPL + (size_t)k * NSLOT;
    *reinterpret_cast<uint4*>(&g_U[base])     = *reinterpret_cast<uint4*>(&hu[0]);
    *reinterpret_cast<uint4*>(&g_U[base + 8]) = *reinterpret_cast<uint4*>(&hu[8]);
    *reinterpret_cast<uint4*>(&g_V[base])     = *reinterpret_cast<uint4*>(&hv[0]);
    *reinterpret_cast<uint4*>(&g_V[base + 8]) = *reinterpret_cast<uint4*>(&hv[8]);
}

// ---------------- K3: 8192x8192x2048 fp16 mma.sync GEMM --------------------
// Block tile 128x128, warp grid 2x4, warp tile 64x32 (4x4 m16n8 frags).
// 2 CTAs/SM, KC=64 chunks, 3-stage ring with mbarrier producer/consumer
// pipeline (no CTA-wide __syncthreads in the mainloop): full[s] armed by
// cp.async.mbarrier.arrive.noinc (count 256), empty[s] armed one-arrive-per-
// warp (count 8). Warps flow with up to 2 stages of skew.
__device__ __forceinline__ float fast_sigmoid(float x) {
    if (x < -88.f) return 0.f;
    return 1.f / (1.f + expf(-x));
}

#define SPAD   72                 // halves per smem row (144 B; conflict-free ldsm)
#define TM     128
#define TN     128
#define KC     64
#define NCHUNK (KSPL / KC)        // 32
#define STAGES 3
#define SA_BYTES (TM * SPAD * 2)  // 18432
#define SB_BYTES (TN * SPAD * 2)  // 18432
#define STAGE_BYTES (SA_BYTES + SB_BYTES)               // 36864
#define MBAR_AREA 128
#define SMEM_PAIR_TOTAL (MBAR_AREA + STAGES * STAGE_BYTES)   // 110720

__global__ __launch_bounds__(256, 2) void pair_kernel(float* __restrict__ out,
                                                      const float* __restrict__ pb) {
    extern __shared__ __align__(128) char smem[];
    uint32_t sbase = smem_u32(smem);
    uint32_t mb_full  = sbase;            // full[s]  at +s*16
    uint32_t mb_empty = sbase + 8;        // empty[s] at +s*16+8
    uint32_t stage0 = sbase + MBAR_AREA;

    int tid = threadIdx.x;
    int lane = tid & 31, wid = tid >> 5;
    int warpM = wid >> 2, warpN = wid & 3;   // 2 x 4 warps; warp tile 64x32

    if (tid == 0) {
#pragma unroll
        for (int s = 0; s < STAGES; s++) {
            MBARRIER_INIT(mb_full + s * 16, 256);
            MBARRIER_INIT(mb_empty + s * 16, 8);
        }
    }
    __syncthreads();

    // tile swizzle: groups of 16 brows x 64 bcols keep wave working set in L2
    int bx = blockIdx.x;                     // 0..4095 (64 brows x 64 bcols)
    int brow = ((bx >> 10) << 4) + ((bx & 1023) >> 6);
    int bcol = bx & 63;
    int i0 = brow * TM, j0 = bcol * TN;

    float acc[4][4][4];
#pragma unroll
    for (int a = 0; a < 4; a++)
#pragma unroll
        for (int b = 0; b < 4; b++)
#pragma unroll
            for (int c = 0; c < 4; c++) acc[a][b][c] = 0.f;

    // cp.async lane mapping: 128 rows x 8 quads(16B); 256 threads -> 4 iters
    int arow[4], aqi[4];
#pragma unroll
    for (int it = 0; it < 4; it++) { int q = tid + it * 256; arow[it] = q >> 3; aqi[it] = q & 7; }

#define ISSUE_CHUNK(c, s) {                                                       \
    uint32_t sa = stage0 + (s) * STAGE_BYTES;                                     \
    uint32_t sb = sa + SA_BYTES;                                                  \
    _Pragma("unroll")                                                             \
    for (int it = 0; it < 4; it++)                                                \
        CP_ASYNC16(sa + (uint32_t)(arow[it] * 144 + aqi[it] * 16),                \
                   &g_U[(size_t)(i0 + arow[it]) * KSPL + (c) * KC + aqi[it] * 8]);\
    _Pragma("unroll")                                                             \
    for (int it = 0; it < 4; it++)                                                \
        CP_ASYNC16(sb + (uint32_t)(arow[it] * 144 + aqi[it] * 16),                \
                   &g_V[(size_t)(j0 + arow[it]) * KSPL + (c) * KC + aqi[it] * 8]);\
    CP_ASYNC_MBAR_ARRIVE(mb_full + (s) * 16); }

    // ldmatrix lane offsets (x4 layout for both A and B)
    int a_m = (lane & 7) + ((lane >> 3) & 1) * 8;   // + warpM*64 + mf*16
    int a_k = ((lane >> 4) & 1) * 8;                // + ks*16
    int b_n = (lane & 7) + ((lane >> 4) & 1) * 8;   // + warpN*32 + nfp*16
    int b_k = ((lane >> 3) & 1) * 8;                // + ks*16

    // prologue: first use of stages 0 and 1 (no empty-wait on first use)
    ISSUE_CHUNK(0, 0);
    ISSUE_CHUNK(1, 1);

#pragma unroll 1
    for (int c = 0; c < NCHUNK; c++) {
        int st = c % STAGES;

        // consumer: wait chunk c resident; use index u = c/3, parity u&1
        MBARRIER_WAIT_PARITY(mb_full + st * 16, (c / 3) & 1);

        uint32_t baseA = stage0 + st * STAGE_BYTES;
        uint32_t baseB = baseA + SA_BYTES;
#pragma unroll
        for (int ks = 0; ks < 4; ks++) {
            uint32_t af[4][4], bf[2][4];
#pragma unroll
            for (int mf = 0; mf < 4; mf++) {
                int mm = warpM * 64 + mf * 16 + a_m;
                int kk = ks * 16 + a_k;
                ldsm_x4(af[mf][0], af[mf][1], af[mf][2], af[mf][3],
                        baseA + (uint32_t)(mm * SPAD + kk) * 2u);
            }
#pragma unroll
            for (int nfp = 0; nfp < 2; nfp++) {
                int nn = warpN * 32 + nfp * 16 + b_n;
                int kk = ks * 16 + b_k;
                ldsm_x4(bf[nfp][0], bf[nfp][1], bf[nfp][2], bf[nfp][3],
                        baseB + (uint32_t)(nn * SPAD + kk) * 2u);
            }
#pragma unroll
            for (int mf = 0; mf < 4; mf++)
#pragma unroll
                for (int nfp = 0; nfp < 2; nfp++) {
                    mma_fp16(acc[mf][2*nfp][0], acc[mf][2*nfp][1],
                             acc[mf][2*nfp][2], acc[mf][2*nfp][3],
                             af[mf][0], af[mf][1], af[mf][2], af[mf][3],
                             bf[nfp][0], bf[nfp][1]);
                    mma_fp16(acc[mf][2*nfp+1][0], acc[mf][2*nfp+1][1],
                             acc[mf][2*nfp+1][2], acc[mf][2*nfp+1][3],
                             af[mf][0], af[mf][1], af[mf][2], af[mf][3],
                             bf[nfp][2], bf[nfp][3]);
                }
        }

        // release stage st (one arrive per warp)
        if (lane == 0) MBARRIER_ARRIVE(mb_empty + st * 16);

        // producer: issue chunk c+2 into stage (c+2)%3
        int cc = c + 2;
        if (cc < NCHUNK) {
            int st2 = cc % STAGES;
            if (cc >= STAGES) {
                // wait for (cc/3 - 1)-th release of this stage
                MBARRIER_WAIT_PARITY(mb_empty + st2 * 16, (cc / 3 - 1) & 1);
            }
            ISSUE_CHUNK(cc, st2);
        }
    }

    // epilogue: x = acc + bias ; sigmoid with exact-underflow fast path
    float bias = *pb;
    int lr = lane >> 2, lc = (lane & 3) * 2;
#pragma unroll
    for (int mf = 0; mf < 4; mf++) {
#pragma unroll
        for (int nf = 0; nf < 4; nf++) {
            int i1 = i0 + warpM * 64 + mf * 16 + lr;
            int j = j0 + warpN * 32 + (nf >> 1) * 16 + (nf & 1) * 8 + lc;
#pragma unroll
            for (int half = 0; half < 2; half++) {
                int i = i1 + half * 8;
                float x0 = acc[mf][nf][half * 2 + 0] + bias;
                float x1 = acc[mf][nf][half * 2 + 1] + bias;
                float2 r;
                r.x = fast_sigmoid(x0);
                r.y = fast_sigmoid(x1);
                *reinterpret_cast<float2*>(&out[(size_t)i * NNODE + j]) = r;
            }
        }
    }
}

// ---------------- launch -----------------------------------------------------
extern "C" void kernel_launch(void* const* d_in, const int* in_sizes, int n_in,
                              void* d_out, int out_size) {
    const float* z     = (const float*)d_in[0];
    const float* gamma = (const float*)d_in[1];
    const float* delta = (const float*)d_in[2];
    const float* Wz    = (const float*)d_in[3];
    const float* Wg    = (const float*)d_in[4];
    const float* Wd    = (const float*)d_in[5];
    const float* pb    = (const float*)d_in[6];
    const float* pwg   = (const float*)d_in[7];
    const float* pwd   = (const float*)d_in[8];
    float* out = (float*)d_out;

    cudaFuncSetAttribute(pair_kernel, cudaFuncAttributeMaxDynamicSharedMemorySize,
                         SMEM_PAIR_TOTAL);
    cudaFuncSetAttribute(gemm_small_tc, cudaFuncAttributeMaxDynamicSharedMemorySize,
                         GS_TOTAL);

    softmax_cols<<<384, 128>>>(Wz, Wg, Wd);
    gemm_small_tc<<<dim3(NNODE / 128, 3), 256, GS_TOTAL>>>(z, gamma, delta, out);
    prep_split<<<NNODE, 128>>>(pwg, pwd);
    pair_kernel<<<4096, 256, SMEM_PAIR_TOTAL>>>(out, pb);
}